// round 6
// baseline (speedup 1.0000x reference)
#include <cuda_runtime.h>

#define DEV_INLINE __device__ __forceinline__
typedef unsigned long long u64;

// ---------------------------------------------------------------------------
// Packed f32x2 helpers (FFMA2 path)
// ---------------------------------------------------------------------------
DEV_INLINE u64 pack2(float x) {
    u64 r;
    asm("mov.b64 %0, {%1, %1};" : "=l"(r) : "r"(__float_as_uint(x)));
    return r;
}
DEV_INLINE u64 pack2(float x, float y) {
    u64 r;
    asm("mov.b64 %0, {%1, %2};" : "=l"(r) : "r"(__float_as_uint(x)), "r"(__float_as_uint(y)));
    return r;
}
DEV_INLINE void fma2(u64& d, u64 a, u64 b) {
    asm("fma.rn.f32x2 %0, %1, %2, %0;" : "+l"(d) : "l"(a), "l"(b));
}
DEV_INLINE float2 unpack2(u64 v) {
    unsigned int lo, hi;
    asm("mov.b64 {%0, %1}, %2;" : "=r"(lo), "=r"(hi) : "l"(v));
    return make_float2(__uint_as_float(lo), __uint_as_float(hi));
}

// cp.async helpers
DEV_INLINE void cp16(float* dst, const float* src) {
    unsigned d = (unsigned)__cvta_generic_to_shared(dst);
    asm volatile("cp.async.cg.shared.global [%0], [%1], 16;" :: "r"(d), "l"(src) : "memory");
}
DEV_INLINE void cp_commit() { asm volatile("cp.async.commit_group;" ::: "memory"); }
template<int N> DEV_INLINE void cp_wait() { asm volatile("cp.async.wait_group %0;" :: "n"(N) : "memory"); }

// ---------------------------------------------------------------------------
// Scratch (device globals — allocation-free rule)
// ---------------------------------------------------------------------------
__device__ float g_qkv[8 * 768 * 1024];     // [b][o][hw]  o: 0..255 Q(scaled), 256..511 K, 512..767 V
__device__ float g_attnf[8 * 256 * 1024];   // scrambled attn output [b][c][hw]

// ---------------------------------------------------------------------------
// GEMM + bias (+ optional Q scaling):  C[b][o][n] = sum_c A[o][c]*B[b][c][n] + bias[o]
// 128x128 block tile, BK=16, 256 threads, 8x8 per-thread, double-buffered smem.
// B fragments read as ulonglong2 (pre-paired f32x2 operands — no packing MOVs).
// ---------------------------------------------------------------------------
template<int K_, bool SCALEQ>
__global__ __launch_bounds__(256, 2)
void gemm_kernel(const float* __restrict__ A, const float* __restrict__ B,
                 const float* __restrict__ bias, float* __restrict__ C, int M)
{
    constexpr int NIT = K_ / 16;
    __shared__ float As[2][16][132];   // k-major, padded
    __shared__ float Bs[2][16][128];

    const int b  = blockIdx.z;
    const int n0 = blockIdx.x * 128;
    const int o0 = blockIdx.y * 128;
    const float* Bb = B + (size_t)b * K_ * 1024;
    float*       Cb = C + (size_t)b * M  * 1024;

    const int tid  = threadIdx.x;
    const int tx   = tid & 15;
    const int ty   = tid >> 4;
    const int arow = tid >> 1;
    const int acol = (tid & 1) * 8;
    const int brow = tid >> 5;
    const int bcol = (tid & 31) * 4;

    u64 acc[8][4];
#pragma unroll
    for (int i = 0; i < 8; ++i)
#pragma unroll
        for (int j = 0; j < 4; ++j) acc[i][j] = 0ull;

    const float* Ag = A  + (size_t)(o0 + arow) * K_ + acol;
    const float* Bg = Bb + (size_t)brow * 1024 + n0 + bcol;

    float4 a0 = *reinterpret_cast<const float4*>(Ag);
    float4 a1 = *reinterpret_cast<const float4*>(Ag + 4);
    float4 b0 = *reinterpret_cast<const float4*>(Bg);
    float4 b1 = *reinterpret_cast<const float4*>(Bg + 8 * 1024);
    {
        As[0][acol + 0][arow] = a0.x; As[0][acol + 1][arow] = a0.y;
        As[0][acol + 2][arow] = a0.z; As[0][acol + 3][arow] = a0.w;
        As[0][acol + 4][arow] = a1.x; As[0][acol + 5][arow] = a1.y;
        As[0][acol + 6][arow] = a1.z; As[0][acol + 7][arow] = a1.w;
        *reinterpret_cast<float4*>(&Bs[0][brow][bcol])     = b0;
        *reinterpret_cast<float4*>(&Bs[0][brow + 8][bcol]) = b1;
    }
    __syncthreads();

    for (int it = 0; it < NIT; ++it) {
        const int cur = it & 1;
        if (it + 1 < NIT) {
            const float* Ag2 = Ag + (it + 1) * 16;
            const float* Bg2 = Bg + (size_t)(it + 1) * 16 * 1024;
            a0 = *reinterpret_cast<const float4*>(Ag2);
            a1 = *reinterpret_cast<const float4*>(Ag2 + 4);
            b0 = *reinterpret_cast<const float4*>(Bg2);
            b1 = *reinterpret_cast<const float4*>(Bg2 + 8 * 1024);
        }

#pragma unroll
        for (int kk = 0; kk < 16; ++kk) {
            float4 aA = *reinterpret_cast<const float4*>(&As[cur][kk][ty * 8]);
            float4 aB = *reinterpret_cast<const float4*>(&As[cur][kk][ty * 8 + 4]);
            ulonglong2 bL = *reinterpret_cast<const ulonglong2*>(&Bs[cur][kk][tx * 4]);
            ulonglong2 bH = *reinterpret_cast<const ulonglong2*>(&Bs[cur][kk][64 + tx * 4]);
            u64 ap;
            ap = pack2(aA.x); fma2(acc[0][0], ap, bL.x); fma2(acc[0][1], ap, bL.y); fma2(acc[0][2], ap, bH.x); fma2(acc[0][3], ap, bH.y);
            ap = pack2(aA.y); fma2(acc[1][0], ap, bL.x); fma2(acc[1][1], ap, bL.y); fma2(acc[1][2], ap, bH.x); fma2(acc[1][3], ap, bH.y);
            ap = pack2(aA.z); fma2(acc[2][0], ap, bL.x); fma2(acc[2][1], ap, bL.y); fma2(acc[2][2], ap, bH.x); fma2(acc[2][3], ap, bH.y);
            ap = pack2(aA.w); fma2(acc[3][0], ap, bL.x); fma2(acc[3][1], ap, bL.y); fma2(acc[3][2], ap, bH.x); fma2(acc[3][3], ap, bH.y);
            ap = pack2(aB.x); fma2(acc[4][0], ap, bL.x); fma2(acc[4][1], ap, bL.y); fma2(acc[4][2], ap, bH.x); fma2(acc[4][3], ap, bH.y);
            ap = pack2(aB.y); fma2(acc[5][0], ap, bL.x); fma2(acc[5][1], ap, bL.y); fma2(acc[5][2], ap, bH.x); fma2(acc[5][3], ap, bH.y);
            ap = pack2(aB.z); fma2(acc[6][0], ap, bL.x); fma2(acc[6][1], ap, bL.y); fma2(acc[6][2], ap, bH.x); fma2(acc[6][3], ap, bH.y);
            ap = pack2(aB.w); fma2(acc[7][0], ap, bL.x); fma2(acc[7][1], ap, bL.y); fma2(acc[7][2], ap, bH.x); fma2(acc[7][3], ap, bH.y);
        }

        if (it + 1 < NIT) {
            const int nb = cur ^ 1;
            As[nb][acol + 0][arow] = a0.x; As[nb][acol + 1][arow] = a0.y;
            As[nb][acol + 2][arow] = a0.z; As[nb][acol + 3][arow] = a0.w;
            As[nb][acol + 4][arow] = a1.x; As[nb][acol + 5][arow] = a1.y;
            As[nb][acol + 6][arow] = a1.z; As[nb][acol + 7][arow] = a1.w;
            *reinterpret_cast<float4*>(&Bs[nb][brow][bcol])     = b0;
            *reinterpret_cast<float4*>(&Bs[nb][brow + 8][bcol]) = b1;
            __syncthreads();
        }
    }

#pragma unroll
    for (int i = 0; i < 8; ++i) {
        const int o = o0 + ty * 8 + i;
        const float bv = bias[o];
        const float sc = (SCALEQ && o < 256) ? 0.17677669529663687f : 1.0f;
        float2 u0 = unpack2(acc[i][0]), u1 = unpack2(acc[i][1]);
        float2 u2 = unpack2(acc[i][2]), u3 = unpack2(acc[i][3]);
        float* cp = Cb + (size_t)o * 1024 + n0;
        *reinterpret_cast<float4*>(cp + tx * 4) =
            make_float4((u0.x + bv) * sc, (u0.y + bv) * sc, (u1.x + bv) * sc, (u1.y + bv) * sc);
        *reinterpret_cast<float4*>(cp + 64 + tx * 4) =
            make_float4((u2.x + bv) * sc, (u2.y + bv) * sc, (u3.x + bv) * sc, (u3.y + bv) * sc);
    }
}

// ---------------------------------------------------------------------------
// Fused attention v3 (softmax over HEADS — local per (q,k)).
// Grid: (q_tile=32, b=8) = 256 CTAs; 256 threads = 8 warps (warp = head).
// 2 CTAs/SM (98 KB smem, <=128 regs) -> single wave, cross-CTA stall coverage.
// k-tile = 16: K double-buffered (cp.async), V single-buffered overlapped
// with Phase A. Each thread owns all 16 keys of the tile for its (head, q).
// smem floats: Qs[256*32] | K 2x[256*16] | V[256*16] | Es[8*16*32] | Rs[16*32]
// ---------------------------------------------------------------------------
__global__ __launch_bounds__(256, 2)
void attn_kernel(const float* __restrict__ qkv, float* __restrict__ attnf)
{
    extern __shared__ float sm[];
    float* Qs   = sm;              // 8192
    float* Kbuf = sm + 8192;       // 2 x 4096
    float* Vs   = sm + 16384;      // 4096
    float* Es   = sm + 20480;      // 4096  [n][k][qi] = n*512 + k*32 + qi
    float* Rs   = sm + 24576;      // 512   [k][qi]

    const int b  = blockIdx.y;
    const int q0 = blockIdx.x * 32;
    const float* QKV = qkv + (size_t)b * 768 * 1024;

    const int tid = threadIdx.x;
    const int n   = tid >> 5;      // head = warp
    const int qi  = tid & 31;

    // ---- load Q tile [256][32] (plain loads, once) ----
#pragma unroll
    for (int c = 0; c < 8; ++c) {
        int i = tid + c * 256;
        int r = i >> 3, cg = (i & 7) * 4;
        *reinterpret_cast<float4*>(&Qs[r * 32 + cg]) =
            *reinterpret_cast<const float4*>(QKV + (size_t)r * 1024 + q0 + cg);
    }

    // ---- prologue: async K(0) ----
#pragma unroll
    for (int c = 0; c < 4; ++c) {
        int i = tid + c * 256;
        int r = i >> 2, cc = (i & 3) * 4;
        cp16(&Kbuf[r * 16 + cc], QKV + (size_t)(256 + r) * 1024 + 0 + cc);
    }
    cp_commit();

    u64 acc[32];
#pragma unroll
    for (int d = 0; d < 32; ++d) acc[d] = 0ull;

    const float* Qp = Qs + n * 1024 + qi;   // Q rows of this head, col qi

    for (int kt = 0; kt < 64; ++kt) {
        const int cur = kt & 1;
        cp_wait<0>();        // K(kt) resident
        __syncthreads();     // all warps past B(kt-1): V buffer + Es free

        // ---- issue V(kt) (overlaps Phase A) ----
        {
            const int k0 = kt * 16;
#pragma unroll
            for (int c = 0; c < 4; ++c) {
                int i = tid + c * 256;
                int r = i >> 2, cc = (i & 3) * 4;
                cp16(&Vs[r * 16 + cc], QKV + (size_t)(512 + r) * 1024 + k0 + cc);
            }
            cp_commit();
        }

        // ---- Phase A: logits for 16 keys, exp -> Es[n][k][qi] ----
        {
            const float* Kb = Kbuf + cur * 4096 + n * 512;
            u64 l2[8];
#pragma unroll
            for (int p = 0; p < 8; ++p) l2[p] = 0ull;
#pragma unroll 4
            for (int d = 0; d < 32; ++d) {
                u64 qq = pack2(Qp[d * 32]);
                ulonglong2 kA = *reinterpret_cast<const ulonglong2*>(Kb + d * 16);
                ulonglong2 kB = *reinterpret_cast<const ulonglong2*>(Kb + d * 16 + 4);
                ulonglong2 kC = *reinterpret_cast<const ulonglong2*>(Kb + d * 16 + 8);
                ulonglong2 kD = *reinterpret_cast<const ulonglong2*>(Kb + d * 16 + 12);
                fma2(l2[0], qq, kA.x); fma2(l2[1], qq, kA.y);
                fma2(l2[2], qq, kB.x); fma2(l2[3], qq, kB.y);
                fma2(l2[4], qq, kC.x); fma2(l2[5], qq, kC.y);
                fma2(l2[6], qq, kD.x); fma2(l2[7], qq, kD.y);
            }
            float* eb = Es + n * 512 + qi;
#pragma unroll
            for (int p = 0; p < 8; ++p) {
                float2 lv = unpack2(l2[p]);
                eb[(2 * p + 0) * 32] = __expf(lv.x);
                eb[(2 * p + 1) * 32] = __expf(lv.y);
            }
        }
        __syncthreads();     // Es complete; K(kt) fully consumed

        // ---- prefetch K(kt+1) into other buffer (overlaps Rs + Phase B) ----
        {
            const int k0n = (kt + 1 < 64) ? (kt + 1) * 16 : 0;   // clamp keeps group count uniform
            float* Kn = Kbuf + (cur ^ 1) * 4096;
#pragma unroll
            for (int c = 0; c < 4; ++c) {
                int i = tid + c * 256;
                int r = i >> 2, cc = (i & 3) * 4;
                cp16(&Kn[r * 16 + cc], QKV + (size_t)(256 + r) * 1024 + k0n + cc);
            }
            cp_commit();
        }

        // ---- Rs pass: Rs[k][qi] = 1 / sum_n Es[n][k][qi] ----
#pragma unroll
        for (int pp = 0; pp < 2; ++pp) {
            int p = tid + pp * 256;
            float s = Es[p] + Es[512 + p] + Es[1024 + p] + Es[1536 + p]
                    + Es[2048 + p] + Es[2560 + p] + Es[3072 + p] + Es[3584 + p];
            Rs[p] = __fdividef(1.0f, s);
        }
        cp_wait<1>();        // V(kt) done (older of {V(kt), K(kt+1)})
        __syncthreads();     // Rs + V visible to all

        // ---- Phase B: weights + PV accumulation ----
        {
            const float* ep = Es + n * 512 + qi;
            const float* rp = Rs + qi;
            u64 wp[8];
#pragma unroll
            for (int j = 0; j < 8; ++j) {
                float w0 = ep[(2 * j + 0) * 32] * rp[(2 * j + 0) * 32];
                float w1 = ep[(2 * j + 1) * 32] * rp[(2 * j + 1) * 32];
                wp[j] = pack2(w0, w1);
            }
            const float* Vb = Vs + n * 512;
#pragma unroll 4
            for (int d = 0; d < 32; ++d) {
                ulonglong2 vA = *reinterpret_cast<const ulonglong2*>(Vb + d * 16);
                ulonglong2 vB = *reinterpret_cast<const ulonglong2*>(Vb + d * 16 + 4);
                ulonglong2 vC = *reinterpret_cast<const ulonglong2*>(Vb + d * 16 + 8);
                ulonglong2 vD = *reinterpret_cast<const ulonglong2*>(Vb + d * 16 + 12);
                fma2(acc[d], wp[0], vA.x); fma2(acc[d], wp[1], vA.y);
                fma2(acc[d], wp[2], vB.x); fma2(acc[d], wp[3], vB.y);
                fma2(acc[d], wp[4], vC.x); fma2(acc[d], wp[5], vC.y);
                fma2(acc[d], wp[6], vD.x); fma2(acc[d], wp[7], vD.y);
            }
        }
        // next iteration's top wait+sync orders V/Es reuse
    }

    // ---- write scrambled output: c = n*32 + tile, hw = qi*32 + d ----
    float* orow = attnf + ((size_t)b * 256 + n * 32 + blockIdx.x) * 1024 + qi * 32;
#pragma unroll
    for (int d4 = 0; d4 < 32; d4 += 4) {
        float2 p0 = unpack2(acc[d4 + 0]);
        float2 p1 = unpack2(acc[d4 + 1]);
        float2 p2 = unpack2(acc[d4 + 2]);
        float2 p3 = unpack2(acc[d4 + 3]);
        *reinterpret_cast<float4*>(orow + d4) =
            make_float4(p0.x + p0.y, p1.x + p1.y, p2.x + p2.y, p3.x + p3.y);
    }
}

// ---------------------------------------------------------------------------
// Launch
// ---------------------------------------------------------------------------
extern "C" void kernel_launch(void* const* d_in, const int* in_sizes, int n_in,
                              void* d_out, int out_size)
{
    (void)in_sizes; (void)n_in; (void)out_size;
    const float* x      = (const float*)d_in[0];   // [8][512][1024]
    const float* w_qkv  = (const float*)d_in[1];   // [768][512]
    const float* b_qkv  = (const float*)d_in[2];   // [768]
    const float* w_attn = (const float*)d_in[3];   // [512][256]
    const float* b_attn = (const float*)d_in[4];   // [512]
    float* out = (float*)d_out;                    // [8][512][1024]

    float *qkv = nullptr, *attnf = nullptr;
    cudaGetSymbolAddress((void**)&qkv, g_qkv);
    cudaGetSymbolAddress((void**)&attnf, g_attnf);

    cudaFuncSetAttribute(attn_kernel,
                         cudaFuncAttributeMaxDynamicSharedMemorySize, 100352);

    // 1) QKV projection + bias, Q rows scaled by 32^-0.5
    gemm_kernel<512, true><<<dim3(8, 6, 8), 256>>>(w_qkv, x, b_qkv, qkv, 768);

    // 2) fused logits / head-softmax / PV with output scramble
    attn_kernel<<<dim3(32, 8), 256, 100352>>>(qkv, attnf);

    // 3) output projection + bias
    gemm_kernel<256, false><<<dim3(8, 4, 8), 256>>>(w_attn, attnf, b_attn, out, 512);
}

// round 11
// speedup vs baseline: 1.0702x; 1.0702x over previous
#include <cuda_runtime.h>

#define DEV_INLINE __device__ __forceinline__
typedef unsigned long long u64;

// ---------------------------------------------------------------------------
// Packed f32x2 helpers (FFMA2 path)
// ---------------------------------------------------------------------------
DEV_INLINE u64 pack2(float x) {
    u64 r;
    asm("mov.b64 %0, {%1, %1};" : "=l"(r) : "r"(__float_as_uint(x)));
    return r;
}
DEV_INLINE u64 pack2(float x, float y) {
    u64 r;
    asm("mov.b64 %0, {%1, %2};" : "=l"(r) : "r"(__float_as_uint(x)), "r"(__float_as_uint(y)));
    return r;
}
DEV_INLINE void fma2(u64& d, u64 a, u64 b) {
    asm("fma.rn.f32x2 %0, %1, %2, %0;" : "+l"(d) : "l"(a), "l"(b));
}
DEV_INLINE float2 unpack2(u64 v) {
    unsigned int lo, hi;
    asm("mov.b64 {%0, %1}, %2;" : "=r"(lo), "=r"(hi) : "l"(v));
    return make_float2(__uint_as_float(lo), __uint_as_float(hi));
}

// base-2 exp via MUFU (single EX2 instruction)
DEV_INLINE float ex2f(float x) {
    float r;
    asm("ex2.approx.f32 %0, %1;" : "=f"(r) : "f"(x));
    return r;
}

// cp.async helpers
DEV_INLINE void cp16(float* dst, const float* src) {
    unsigned d = (unsigned)__cvta_generic_to_shared(dst);
    asm volatile("cp.async.cg.shared.global [%0], [%1], 16;" :: "r"(d), "l"(src) : "memory");
}
DEV_INLINE void cp_commit() { asm volatile("cp.async.commit_group;" ::: "memory"); }
template<int N> DEV_INLINE void cp_wait() { asm volatile("cp.async.wait_group %0;" :: "n"(N) : "memory"); }

// ---------------------------------------------------------------------------
// Scratch (device globals — allocation-free rule)
// ---------------------------------------------------------------------------
__device__ float g_qkv[8 * 768 * 1024];     // [b][o][hw]  o: 0..255 Q(scaled), 256..511 K, 512..767 V
__device__ float g_attnf[8 * 256 * 1024];   // scrambled attn output [b][c][hw]

// ---------------------------------------------------------------------------
// GEMM + bias (+ optional Q scaling):  C[b][o][n] = sum_c A[o][c]*B[b][c][n] + bias[o]
// 128x128 block tile, BK=16, 256 threads, 8x8 per-thread, double-buffered smem.
// (R5 version — measured 135.3us on GEMM1.)
// Q rows are scaled by 1/sqrt(dk) * 1/ln(2): attention then uses exp2.
// ---------------------------------------------------------------------------
template<int K_, bool SCALEQ>
__global__ __launch_bounds__(256, 2)
void gemm_kernel(const float* __restrict__ A, const float* __restrict__ B,
                 const float* __restrict__ bias, float* __restrict__ C, int M)
{
    constexpr int NIT = K_ / 16;
    __shared__ float As[2][16][132];   // k-major, padded
    __shared__ float Bs[2][16][128];

    const int b  = blockIdx.z;
    const int n0 = blockIdx.x * 128;
    const int o0 = blockIdx.y * 128;
    const float* Bb = B + (size_t)b * K_ * 1024;
    float*       Cb = C + (size_t)b * M  * 1024;

    const int tid  = threadIdx.x;
    const int tx   = tid & 15;
    const int ty   = tid >> 4;
    const int arow = tid >> 1;
    const int acol = (tid & 1) * 8;
    const int brow = tid >> 5;
    const int bcol = (tid & 31) * 4;

    u64 acc[8][4];
#pragma unroll
    for (int i = 0; i < 8; ++i)
#pragma unroll
        for (int j = 0; j < 4; ++j) acc[i][j] = 0ull;

    const float* Ag = A  + (size_t)(o0 + arow) * K_ + acol;
    const float* Bg = Bb + (size_t)brow * 1024 + n0 + bcol;

    float4 a0 = *reinterpret_cast<const float4*>(Ag);
    float4 a1 = *reinterpret_cast<const float4*>(Ag + 4);
    float4 b0 = *reinterpret_cast<const float4*>(Bg);
    float4 b1 = *reinterpret_cast<const float4*>(Bg + 8 * 1024);
    {
        As[0][acol + 0][arow] = a0.x; As[0][acol + 1][arow] = a0.y;
        As[0][acol + 2][arow] = a0.z; As[0][acol + 3][arow] = a0.w;
        As[0][acol + 4][arow] = a1.x; As[0][acol + 5][arow] = a1.y;
        As[0][acol + 6][arow] = a1.z; As[0][acol + 7][arow] = a1.w;
        *reinterpret_cast<float4*>(&Bs[0][brow][bcol])     = b0;
        *reinterpret_cast<float4*>(&Bs[0][brow + 8][bcol]) = b1;
    }
    __syncthreads();

    for (int it = 0; it < NIT; ++it) {
        const int cur = it & 1;
        if (it + 1 < NIT) {
            const float* Ag2 = Ag + (it + 1) * 16;
            const float* Bg2 = Bg + (size_t)(it + 1) * 16 * 1024;
            a0 = *reinterpret_cast<const float4*>(Ag2);
            a1 = *reinterpret_cast<const float4*>(Ag2 + 4);
            b0 = *reinterpret_cast<const float4*>(Bg2);
            b1 = *reinterpret_cast<const float4*>(Bg2 + 8 * 1024);
        }

#pragma unroll
        for (int kk = 0; kk < 16; ++kk) {
            float4 aA = *reinterpret_cast<const float4*>(&As[cur][kk][ty * 8]);
            float4 aB = *reinterpret_cast<const float4*>(&As[cur][kk][ty * 8 + 4]);
            float4 bA = *reinterpret_cast<const float4*>(&Bs[cur][kk][tx * 4]);
            float4 bB = *reinterpret_cast<const float4*>(&Bs[cur][kk][64 + tx * 4]);
            u64 bp0 = pack2(bA.x, bA.y), bp1 = pack2(bA.z, bA.w);
            u64 bp2 = pack2(bB.x, bB.y), bp3 = pack2(bB.z, bB.w);
            u64 ap;
            ap = pack2(aA.x); fma2(acc[0][0], ap, bp0); fma2(acc[0][1], ap, bp1); fma2(acc[0][2], ap, bp2); fma2(acc[0][3], ap, bp3);
            ap = pack2(aA.y); fma2(acc[1][0], ap, bp0); fma2(acc[1][1], ap, bp1); fma2(acc[1][2], ap, bp2); fma2(acc[1][3], ap, bp3);
            ap = pack2(aA.z); fma2(acc[2][0], ap, bp0); fma2(acc[2][1], ap, bp1); fma2(acc[2][2], ap, bp2); fma2(acc[2][3], ap, bp3);
            ap = pack2(aA.w); fma2(acc[3][0], ap, bp0); fma2(acc[3][1], ap, bp1); fma2(acc[3][2], ap, bp2); fma2(acc[3][3], ap, bp3);
            ap = pack2(aB.x); fma2(acc[4][0], ap, bp0); fma2(acc[4][1], ap, bp1); fma2(acc[4][2], ap, bp2); fma2(acc[4][3], ap, bp3);
            ap = pack2(aB.y); fma2(acc[5][0], ap, bp0); fma2(acc[5][1], ap, bp1); fma2(acc[5][2], ap, bp2); fma2(acc[5][3], ap, bp3);
            ap = pack2(aB.z); fma2(acc[6][0], ap, bp0); fma2(acc[6][1], ap, bp1); fma2(acc[6][2], ap, bp2); fma2(acc[6][3], ap, bp3);
            ap = pack2(aB.w); fma2(acc[7][0], ap, bp0); fma2(acc[7][1], ap, bp1); fma2(acc[7][2], ap, bp2); fma2(acc[7][3], ap, bp3);
        }

        if (it + 1 < NIT) {
            const int nb = cur ^ 1;
            As[nb][acol + 0][arow] = a0.x; As[nb][acol + 1][arow] = a0.y;
            As[nb][acol + 2][arow] = a0.z; As[nb][acol + 3][arow] = a0.w;
            As[nb][acol + 4][arow] = a1.x; As[nb][acol + 5][arow] = a1.y;
            As[nb][acol + 6][arow] = a1.z; As[nb][acol + 7][arow] = a1.w;
            *reinterpret_cast<float4*>(&Bs[nb][brow][bcol])     = b0;
            *reinterpret_cast<float4*>(&Bs[nb][brow + 8][bcol]) = b1;
            __syncthreads();
        }
    }

    // scale = 1/sqrt(32) * 1/ln(2)  (exp2-based softmax downstream)
    constexpr float QSC = 0.17677669529663687f * 1.4426950408889634f;
#pragma unroll
    for (int i = 0; i < 8; ++i) {
        const int o = o0 + ty * 8 + i;
        const float bv = bias[o];
        const float sc = (SCALEQ && o < 256) ? QSC : 1.0f;
        float2 u0 = unpack2(acc[i][0]), u1 = unpack2(acc[i][1]);
        float2 u2 = unpack2(acc[i][2]), u3 = unpack2(acc[i][3]);
        float* cp = Cb + (size_t)o * 1024 + n0;
        *reinterpret_cast<float4*>(cp + tx * 4) =
            make_float4((u0.x + bv) * sc, (u0.y + bv) * sc, (u1.x + bv) * sc, (u1.y + bv) * sc);
        *reinterpret_cast<float4*>(cp + 64 + tx * 4) =
            make_float4((u2.x + bv) * sc, (u2.y + bv) * sc, (u3.x + bv) * sc, (u3.y + bv) * sc);
    }
}

// ---------------------------------------------------------------------------
// Fused attention v4 (R5 skeleton + micro-opts).
// Grid: (q_tile=32, b=8). 512 threads = 16 warps = (head n, k-half h).
// Softmax over HEADS: local per (q,k) -> Es exchange + Rs reciprocal sums.
// vs R5: Q transposed [n][q][36] (float4 d-reads), own-e kept in registers
// for Phase B, ex2.approx instead of __expf (Q pre-scaled by 1/ln2 in GEMM1),
// Phase B hoists all 8 weight pairs then streams V once.
// smem floats: Qs 9216 | K 2x8192 | V 2x8192 | Es 8192 | Rs 1024  (200 KB)
// ---------------------------------------------------------------------------
__global__ __launch_bounds__(512, 1)
void attn_kernel(const float* __restrict__ qkv, float* __restrict__ attnf)
{
    extern __shared__ float sm[];
    float* Qs   = sm;              // [256][36]  row = n*32+q, padded
    float* Kbuf = sm + 9216;       // 2 x [256][32]
    float* Vbuf = sm + 25600;      // 2 x [256][32]
    float* Es   = sm + 41984;      // [8][32][32] = [n][k][qi]
    float* Rs   = sm + 50176;      // [32][32]    = [k][qi]

    const int b  = blockIdx.y;
    const int q0 = blockIdx.x * 32;
    const float* QKV = qkv + (size_t)b * 768 * 1024;

    const int tid  = threadIdx.x;
    const int warp = tid >> 5;
    const int n    = warp >> 1;     // head
    const int h    = warp & 1;      // k-half (16 keys)
    const int qi   = tid & 31;

    // ---- load Q tile, transposed into [n][q][36] ----
#pragma unroll
    for (int c = 0; c < 4; ++c) {
        int i = tid + c * 512;
        int r = i >> 3, cg = (i & 7) * 4;     // r = n*32+d
        float4 v = *reinterpret_cast<const float4*>(QKV + (size_t)r * 1024 + q0 + cg);
        int nn = r >> 5, d = r & 31;
        Qs[(nn * 32 + cg + 0) * 36 + d] = v.x;
        Qs[(nn * 32 + cg + 1) * 36 + d] = v.y;
        Qs[(nn * 32 + cg + 2) * 36 + d] = v.z;
        Qs[(nn * 32 + cg + 3) * 36 + d] = v.w;
    }

    // ---- prologue: async K(0), V(0) ----
#pragma unroll
    for (int c = 0; c < 4; ++c) {
        int i = tid + c * 512;
        int r = i >> 3, cg = (i & 7) * 4;
        cp16(&Kbuf[r * 32 + cg], QKV + (size_t)(256 + r) * 1024 + 0 + cg);
        cp16(&Vbuf[r * 32 + cg], QKV + (size_t)(512 + r) * 1024 + 0 + cg);
    }
    cp_commit();

    u64 acc[32];
#pragma unroll
    for (int d = 0; d < 32; ++d) acc[d] = 0ull;

    const float* Qrow = Qs + (n * 32 + qi) * 36;   // this thread's Q[d] vector

    for (int kt = 0; kt < 32; ++kt) {
        const int cur = kt & 1;
        cp_wait<0>();
        __syncthreads();   // K/V(kt) visible; everyone past phase B(kt-1)

        if (kt < 31) {     // prefetch kt+1 (overlaps phases A+B)
            const int k0 = (kt + 1) * 32;
            float* Kn = Kbuf + (cur ^ 1) * 8192;
            float* Vn = Vbuf + (cur ^ 1) * 8192;
#pragma unroll
            for (int c = 0; c < 4; ++c) {
                int i = tid + c * 512;
                int r = i >> 3, cg = (i & 7) * 4;
                cp16(&Kn[r * 32 + cg], QKV + (size_t)(256 + r) * 1024 + k0 + cg);
                cp16(&Vn[r * 32 + cg], QKV + (size_t)(512 + r) * 1024 + k0 + cg);
            }
            cp_commit();
        }

        const float* K = Kbuf + cur * 8192;
        const float* V = Vbuf + cur * 8192;
        float eo[16];   // own exp values, live into phase B

        // ---- Phase A: logits for my 16 keys, exp2 -> regs + Es[n][k][qi] ----
        {
            const float* Kp = K + n * 1024 + h * 16;
            u64 l2[8];
#pragma unroll
            for (int p = 0; p < 8; ++p) l2[p] = 0ull;
#pragma unroll 2
            for (int d4 = 0; d4 < 8; ++d4) {
                float4 qv = *reinterpret_cast<const float4*>(Qrow + d4 * 4);
                float qa[4] = {qv.x, qv.y, qv.z, qv.w};
#pragma unroll
                for (int dd = 0; dd < 4; ++dd) {
                    const int d = d4 * 4 + dd;
                    u64 qq = pack2(qa[dd]);
                    ulonglong2 kA = *reinterpret_cast<const ulonglong2*>(Kp + d * 32);
                    ulonglong2 kB = *reinterpret_cast<const ulonglong2*>(Kp + d * 32 + 4);
                    ulonglong2 kC = *reinterpret_cast<const ulonglong2*>(Kp + d * 32 + 8);
                    ulonglong2 kD = *reinterpret_cast<const ulonglong2*>(Kp + d * 32 + 12);
                    fma2(l2[0], qq, kA.x); fma2(l2[1], qq, kA.y);
                    fma2(l2[2], qq, kB.x); fma2(l2[3], qq, kB.y);
                    fma2(l2[4], qq, kC.x); fma2(l2[5], qq, kC.y);
                    fma2(l2[6], qq, kD.x); fma2(l2[7], qq, kD.y);
                }
            }
            float* eb = Es + n * 1024 + (h * 16) * 32 + qi;
#pragma unroll
            for (int p = 0; p < 8; ++p) {
                float2 lv = unpack2(l2[p]);
                float e0 = ex2f(lv.x);
                float e1 = ex2f(lv.y);
                eo[2 * p + 0] = e0;
                eo[2 * p + 1] = e1;
                eb[(2 * p + 0) * 32] = e0;
                eb[(2 * p + 1) * 32] = e1;
            }
        }
        __syncthreads();     // Es complete; K(kt) consumed

        // ---- Rs pass: Rs[k][qi] = 1 / sum_n Es[n][k][qi] ----
#pragma unroll
        for (int pp = 0; pp < 2; ++pp) {
            int p = tid + pp * 512;
            float s = Es[p] + Es[1024 + p] + Es[2048 + p] + Es[3072 + p]
                    + Es[4096 + p] + Es[5120 + p] + Es[6144 + p] + Es[7168 + p];
            Rs[p] = __fdividef(1.0f, s);
        }
        __syncthreads();     // Rs visible

        // ---- Phase B: weights (regs) + PV accumulation ----
        {
            const float* rp = Rs + (h * 16) * 32 + qi;
            u64 wp[8];
#pragma unroll
            for (int j = 0; j < 8; ++j) {
                float w0 = eo[2 * j + 0] * rp[(2 * j + 0) * 32];
                float w1 = eo[2 * j + 1] * rp[(2 * j + 1) * 32];
                wp[j] = pack2(w0, w1);
            }
            const float* Vp = V + n * 1024 + h * 16;
#pragma unroll 4
            for (int d = 0; d < 32; ++d) {
                ulonglong2 vA = *reinterpret_cast<const ulonglong2*>(Vp + d * 32);
                ulonglong2 vB = *reinterpret_cast<const ulonglong2*>(Vp + d * 32 + 4);
                ulonglong2 vC = *reinterpret_cast<const ulonglong2*>(Vp + d * 32 + 8);
                ulonglong2 vD = *reinterpret_cast<const ulonglong2*>(Vp + d * 32 + 12);
                fma2(acc[d], wp[0], vA.x); fma2(acc[d], wp[1], vA.y);
                fma2(acc[d], wp[2], vB.x); fma2(acc[d], wp[3], vB.y);
                fma2(acc[d], wp[4], vC.x); fma2(acc[d], wp[5], vC.y);
                fma2(acc[d], wp[6], vD.x); fma2(acc[d], wp[7], vD.y);
            }
        }
        // next iteration's top wait+sync orders buffer/Es reuse
    }

    // ---- merge k-halves, write scrambled output ----
    __syncthreads();   // all phase B done; Es/Rs reusable as staging
    float res[32];
#pragma unroll
    for (int d = 0; d < 32; ++d) {
        float2 u = unpack2(acc[d]);
        res[d] = u.x + u.y;
    }
    float* stage = Es;                       // pitch 36 (uses Es+Rs space)
    float* srow = stage + (n * 32 + qi) * 36;
    if (h == 0) {
#pragma unroll
        for (int d = 0; d < 32; d += 4)
            *reinterpret_cast<float4*>(&srow[d]) =
                make_float4(res[d], res[d + 1], res[d + 2], res[d + 3]);
    }
    __syncthreads();
    if (h == 1) {
        float* orow = attnf + ((size_t)b * 256 + n * 32 + blockIdx.x) * 1024 + qi * 32;
#pragma unroll
        for (int d = 0; d < 32; d += 4) {
            float4 o = *reinterpret_cast<const float4*>(&srow[d]);
            *reinterpret_cast<float4*>(orow + d) =
                make_float4(res[d] + o.x, res[d + 1] + o.y, res[d + 2] + o.z, res[d + 3] + o.w);
        }
    }
}

// ---------------------------------------------------------------------------
// Launch
// ---------------------------------------------------------------------------
extern "C" void kernel_launch(void* const* d_in, const int* in_sizes, int n_in,
                              void* d_out, int out_size)
{
    (void)in_sizes; (void)n_in; (void)out_size;
    const float* x      = (const float*)d_in[0];   // [8][512][1024]
    const float* w_qkv  = (const float*)d_in[1];   // [768][512]
    const float* b_qkv  = (const float*)d_in[2];   // [768]
    const float* w_attn = (const float*)d_in[3];   // [512][256]
    const float* b_attn = (const float*)d_in[4];   // [512]
    float* out = (float*)d_out;                    // [8][512][1024]

    float *qkv = nullptr, *attnf = nullptr;
    cudaGetSymbolAddress((void**)&qkv, g_qkv);
    cudaGetSymbolAddress((void**)&attnf, g_attnf);

    cudaFuncSetAttribute(attn_kernel,
                         cudaFuncAttributeMaxDynamicSharedMemorySize, 204800);

    // 1) QKV projection + bias, Q rows scaled by 1/sqrt(32)/ln(2)
    gemm_kernel<512, true><<<dim3(8, 6, 8), 256>>>(w_qkv, x, b_qkv, qkv, 768);

    // 2) fused logits / head-softmax(exp2) / PV with output scramble
    attn_kernel<<<dim3(32, 8), 512, 204800>>>(qkv, attnf);

    // 3) output projection + bias
    gemm_kernel<256, false><<<dim3(8, 4, 8), 256>>>(w_attn, attnf, b_attn, out, 512);
}

// round 12
// speedup vs baseline: 1.2014x; 1.1226x over previous
#include <cuda_runtime.h>

#define DEV_INLINE __device__ __forceinline__
typedef unsigned long long u64;

// ---------------------------------------------------------------------------
// Packed f32x2 helpers (FFMA2 path)
// ---------------------------------------------------------------------------
DEV_INLINE u64 pack2(float x) {
    u64 r;
    asm("mov.b64 %0, {%1, %1};" : "=l"(r) : "r"(__float_as_uint(x)));
    return r;
}
DEV_INLINE u64 pack2(float x, float y) {
    u64 r;
    asm("mov.b64 %0, {%1, %2};" : "=l"(r) : "r"(__float_as_uint(x)), "r"(__float_as_uint(y)));
    return r;
}
DEV_INLINE void fma2(u64& d, u64 a, u64 b) {
    asm("fma.rn.f32x2 %0, %1, %2, %0;" : "+l"(d) : "l"(a), "l"(b));
}
DEV_INLINE float2 unpack2(u64 v) {
    unsigned int lo, hi;
    asm("mov.b64 {%0, %1}, %2;" : "=r"(lo), "=r"(hi) : "l"(v));
    return make_float2(__uint_as_float(lo), __uint_as_float(hi));
}

// base-2 exp via MUFU (single EX2 instruction)
DEV_INLINE float ex2f(float x) {
    float r;
    asm("ex2.approx.f32 %0, %1;" : "=f"(r) : "f"(x));
    return r;
}

// cp.async helpers
DEV_INLINE void cp16(float* dst, const float* src) {
    unsigned d = (unsigned)__cvta_generic_to_shared(dst);
    asm volatile("cp.async.cg.shared.global [%0], [%1], 16;" :: "r"(d), "l"(src) : "memory");
}
DEV_INLINE void cp_commit() { asm volatile("cp.async.commit_group;" ::: "memory"); }
template<int N> DEV_INLINE void cp_wait() { asm volatile("cp.async.wait_group %0;" :: "n"(N) : "memory"); }

// ---------------------------------------------------------------------------
// Scratch (device globals — allocation-free rule)
// ---------------------------------------------------------------------------
__device__ float g_qkv[8 * 768 * 1024];     // [b][o][hw]  o: 0..255 Q(scaled), 256..511 K, 512..767 V
__device__ float g_attnf[8 * 256 * 1024];   // scrambled attn output [b][c][hw]

// ---------------------------------------------------------------------------
// GEMM + bias (+ optional Q scaling):  C[b][o][n] = sum_c A[o][c]*B[b][c][n] + bias[o]
// 128x128 block tile, BK=16, 256 threads, 8x8 per-thread, double-buffered smem.
// (R5 version — measured ~134us on GEMM1.)
// Q rows scaled by 1/sqrt(dk)/ln(2): attention uses exp2.
// ---------------------------------------------------------------------------
template<int K_, bool SCALEQ>
__global__ __launch_bounds__(256, 2)
void gemm_kernel(const float* __restrict__ A, const float* __restrict__ B,
                 const float* __restrict__ bias, float* __restrict__ C, int M)
{
    constexpr int NIT = K_ / 16;
    __shared__ float As[2][16][132];   // k-major, padded
    __shared__ float Bs[2][16][128];

    const int b  = blockIdx.z;
    const int n0 = blockIdx.x * 128;
    const int o0 = blockIdx.y * 128;
    const float* Bb = B + (size_t)b * K_ * 1024;
    float*       Cb = C + (size_t)b * M  * 1024;

    const int tid  = threadIdx.x;
    const int tx   = tid & 15;
    const int ty   = tid >> 4;
    const int arow = tid >> 1;
    const int acol = (tid & 1) * 8;
    const int brow = tid >> 5;
    const int bcol = (tid & 31) * 4;

    u64 acc[8][4];
#pragma unroll
    for (int i = 0; i < 8; ++i)
#pragma unroll
        for (int j = 0; j < 4; ++j) acc[i][j] = 0ull;

    const float* Ag = A  + (size_t)(o0 + arow) * K_ + acol;
    const float* Bg = Bb + (size_t)brow * 1024 + n0 + bcol;

    float4 a0 = *reinterpret_cast<const float4*>(Ag);
    float4 a1 = *reinterpret_cast<const float4*>(Ag + 4);
    float4 b0 = *reinterpret_cast<const float4*>(Bg);
    float4 b1 = *reinterpret_cast<const float4*>(Bg + 8 * 1024);
    {
        As[0][acol + 0][arow] = a0.x; As[0][acol + 1][arow] = a0.y;
        As[0][acol + 2][arow] = a0.z; As[0][acol + 3][arow] = a0.w;
        As[0][acol + 4][arow] = a1.x; As[0][acol + 5][arow] = a1.y;
        As[0][acol + 6][arow] = a1.z; As[0][acol + 7][arow] = a1.w;
        *reinterpret_cast<float4*>(&Bs[0][brow][bcol])     = b0;
        *reinterpret_cast<float4*>(&Bs[0][brow + 8][bcol]) = b1;
    }
    __syncthreads();

    for (int it = 0; it < NIT; ++it) {
        const int cur = it & 1;
        if (it + 1 < NIT) {
            const float* Ag2 = Ag + (it + 1) * 16;
            const float* Bg2 = Bg + (size_t)(it + 1) * 16 * 1024;
            a0 = *reinterpret_cast<const float4*>(Ag2);
            a1 = *reinterpret_cast<const float4*>(Ag2 + 4);
            b0 = *reinterpret_cast<const float4*>(Bg2);
            b1 = *reinterpret_cast<const float4*>(Bg2 + 8 * 1024);
        }

#pragma unroll
        for (int kk = 0; kk < 16; ++kk) {
            float4 aA = *reinterpret_cast<const float4*>(&As[cur][kk][ty * 8]);
            float4 aB = *reinterpret_cast<const float4*>(&As[cur][kk][ty * 8 + 4]);
            float4 bA = *reinterpret_cast<const float4*>(&Bs[cur][kk][tx * 4]);
            float4 bB = *reinterpret_cast<const float4*>(&Bs[cur][kk][64 + tx * 4]);
            u64 bp0 = pack2(bA.x, bA.y), bp1 = pack2(bA.z, bA.w);
            u64 bp2 = pack2(bB.x, bB.y), bp3 = pack2(bB.z, bB.w);
            u64 ap;
            ap = pack2(aA.x); fma2(acc[0][0], ap, bp0); fma2(acc[0][1], ap, bp1); fma2(acc[0][2], ap, bp2); fma2(acc[0][3], ap, bp3);
            ap = pack2(aA.y); fma2(acc[1][0], ap, bp0); fma2(acc[1][1], ap, bp1); fma2(acc[1][2], ap, bp2); fma2(acc[1][3], ap, bp3);
            ap = pack2(aA.z); fma2(acc[2][0], ap, bp0); fma2(acc[2][1], ap, bp1); fma2(acc[2][2], ap, bp2); fma2(acc[2][3], ap, bp3);
            ap = pack2(aA.w); fma2(acc[3][0], ap, bp0); fma2(acc[3][1], ap, bp1); fma2(acc[3][2], ap, bp2); fma2(acc[3][3], ap, bp3);
            ap = pack2(aB.x); fma2(acc[4][0], ap, bp0); fma2(acc[4][1], ap, bp1); fma2(acc[4][2], ap, bp2); fma2(acc[4][3], ap, bp3);
            ap = pack2(aB.y); fma2(acc[5][0], ap, bp0); fma2(acc[5][1], ap, bp1); fma2(acc[5][2], ap, bp2); fma2(acc[5][3], ap, bp3);
            ap = pack2(aB.z); fma2(acc[6][0], ap, bp0); fma2(acc[6][1], ap, bp1); fma2(acc[6][2], ap, bp2); fma2(acc[6][3], ap, bp3);
            ap = pack2(aB.w); fma2(acc[7][0], ap, bp0); fma2(acc[7][1], ap, bp1); fma2(acc[7][2], ap, bp2); fma2(acc[7][3], ap, bp3);
        }

        if (it + 1 < NIT) {
            const int nb = cur ^ 1;
            As[nb][acol + 0][arow] = a0.x; As[nb][acol + 1][arow] = a0.y;
            As[nb][acol + 2][arow] = a0.z; As[nb][acol + 3][arow] = a0.w;
            As[nb][acol + 4][arow] = a1.x; As[nb][acol + 5][arow] = a1.y;
            As[nb][acol + 6][arow] = a1.z; As[nb][acol + 7][arow] = a1.w;
            *reinterpret_cast<float4*>(&Bs[nb][brow][bcol])     = b0;
            *reinterpret_cast<float4*>(&Bs[nb][brow + 8][bcol]) = b1;
            __syncthreads();
        }
    }

    // scale = 1/sqrt(32) * 1/ln(2)  (exp2-based softmax downstream)
    constexpr float QSC = 0.17677669529663687f * 1.4426950408889634f;
#pragma unroll
    for (int i = 0; i < 8; ++i) {
        const int o = o0 + ty * 8 + i;
        const float bv = bias[o];
        const float sc = (SCALEQ && o < 256) ? QSC : 1.0f;
        float2 u0 = unpack2(acc[i][0]), u1 = unpack2(acc[i][1]);
        float2 u2 = unpack2(acc[i][2]), u3 = unpack2(acc[i][3]);
        float* cp = Cb + (size_t)o * 1024 + n0;
        *reinterpret_cast<float4*>(cp + tx * 4) =
            make_float4((u0.x + bv) * sc, (u0.y + bv) * sc, (u1.x + bv) * sc, (u1.y + bv) * sc);
        *reinterpret_cast<float4*>(cp + 64 + tx * 4) =
            make_float4((u2.x + bv) * sc, (u2.y + bv) * sc, (u3.x + bv) * sc, (u3.y + bv) * sc);
    }
}

// ---------------------------------------------------------------------------
// Fused attention v5: single-wave, 2 CTAs/SM.
// Grid: (q_tile=32, b=8) = 256 CTAs; 256 threads = 8 warps (warp = head).
// Thread (n, qi) owns ALL 32 keys of each k-tile. k-tile = 32, 32 iterations.
// Q read via LDG (same 32 addrs every kt -> L1-resident). K single-buffered
// with prefetch-after-use; V single-buffered, load overlaps Phase A.
// smem floats: K[256][32] | V[256][32] | Es[8][32][32] | Rs[32][32] = 100 KB.
// Output: each thread owns its full 32-d row -> direct coalesced store.
// ---------------------------------------------------------------------------
__global__ __launch_bounds__(256, 2)
void attn_kernel(const float* __restrict__ qkv, float* __restrict__ attnf)
{
    extern __shared__ float sm[];
    float* Ksm = sm;              // [256][32]  row = n*32+d
    float* Vsm = sm + 8192;       // [256][32]
    float* Es  = sm + 16384;      // [8][32][32] = [n][k][qi]
    float* Rs  = sm + 24576;      // [32][32]    = [k][qi]

    const int b  = blockIdx.y;
    const int qt = blockIdx.x;
    const int q0 = qt * 32;
    const float* QKV = qkv + (size_t)b * 768 * 1024;

    const int tid = threadIdx.x;
    const int n   = tid >> 5;      // head = warp
    const int qi  = tid & 31;

    // loader indices: 2048 cp16 per 8K-float tile, 8 per thread
    const int lr = tid >> 3;            // row base 0..31 (step 32)
    const int lc = (tid & 7) * 4;       // col 0..28

    // ---- prologue: async K(0) ----
#pragma unroll
    for (int c = 0; c < 8; ++c) {
        int r = lr + c * 32;
        cp16(&Ksm[r * 32 + lc], QKV + (size_t)(256 + r) * 1024 + 0 + lc);
    }
    cp_commit();

    u64 acc[32];
#pragma unroll
    for (int d = 0; d < 32; ++d) acc[d] = 0ull;

    // Q[n*32+d][q0+qi] = Qg[d*1024]; identical every kt -> L1-hot
    const float* Qg = QKV + (size_t)(n * 32) * 1024 + q0 + qi;

    for (int kt = 0; kt < 32; ++kt) {
        cp_wait<0>();        // K(kt) resident
        __syncthreads();     // all past phase B(kt-1): V buffer + Es free

        // ---- issue V(kt) (lands during Phase A) ----
        {
            const int k0 = kt * 32;
#pragma unroll
            for (int c = 0; c < 8; ++c) {
                int r = lr + c * 32;
                cp16(&Vsm[r * 32 + lc], QKV + (size_t)(512 + r) * 1024 + k0 + lc);
            }
            cp_commit();
        }

        // ---- Phase A: logits for 32 keys -> exp2 -> Es[n][k][qi] ----
        {
            const float* Kb = Ksm + n * 1024;
            u64 l2[16];
#pragma unroll
            for (int p = 0; p < 16; ++p) l2[p] = 0ull;
#pragma unroll 4
            for (int d = 0; d < 32; ++d) {
                u64 qq = pack2(Qg[d * 1024]);
                const float* kr = Kb + d * 32;
                ulonglong2 kA = *reinterpret_cast<const ulonglong2*>(kr);
                ulonglong2 kB = *reinterpret_cast<const ulonglong2*>(kr + 4);
                ulonglong2 kC = *reinterpret_cast<const ulonglong2*>(kr + 8);
                ulonglong2 kD = *reinterpret_cast<const ulonglong2*>(kr + 12);
                ulonglong2 kE = *reinterpret_cast<const ulonglong2*>(kr + 16);
                ulonglong2 kF = *reinterpret_cast<const ulonglong2*>(kr + 20);
                ulonglong2 kG = *reinterpret_cast<const ulonglong2*>(kr + 24);
                ulonglong2 kH = *reinterpret_cast<const ulonglong2*>(kr + 28);
                fma2(l2[0],  qq, kA.x); fma2(l2[1],  qq, kA.y);
                fma2(l2[2],  qq, kB.x); fma2(l2[3],  qq, kB.y);
                fma2(l2[4],  qq, kC.x); fma2(l2[5],  qq, kC.y);
                fma2(l2[6],  qq, kD.x); fma2(l2[7],  qq, kD.y);
                fma2(l2[8],  qq, kE.x); fma2(l2[9],  qq, kE.y);
                fma2(l2[10], qq, kF.x); fma2(l2[11], qq, kF.y);
                fma2(l2[12], qq, kG.x); fma2(l2[13], qq, kG.y);
                fma2(l2[14], qq, kH.x); fma2(l2[15], qq, kH.y);
            }
            float* eb = Es + n * 1024 + qi;
#pragma unroll
            for (int p = 0; p < 16; ++p) {
                float2 lv = unpack2(l2[p]);
                eb[(2 * p + 0) * 32] = ex2f(lv.x);
                eb[(2 * p + 1) * 32] = ex2f(lv.y);
            }
        }
        __syncthreads();     // Es complete; K(kt) fully consumed

        // ---- prefetch K(kt+1) into the SAME buffer (overlaps Rs + Phase B) ----
        {
            const int k0n = (kt + 1 < 32) ? (kt + 1) * 32 : 0;  // uniform group count
#pragma unroll
            for (int c = 0; c < 8; ++c) {
                int r = lr + c * 32;
                cp16(&Ksm[r * 32 + lc], QKV + (size_t)(256 + r) * 1024 + k0n + lc);
            }
            cp_commit();
        }

        // ---- Rs pass: Rs[k][qi] = 1 / sum_n Es[n][k][qi] ----
#pragma unroll
        for (int pp = 0; pp < 4; ++pp) {
            int p = tid + pp * 256;
            float s = Es[p] + Es[1024 + p] + Es[2048 + p] + Es[3072 + p]
                    + Es[4096 + p] + Es[5120 + p] + Es[6144 + p] + Es[7168 + p];
            Rs[p] = __fdividef(1.0f, s);
        }
        cp_wait<1>();        // V(kt) done (older of {V(kt), K(kt+1)})
        __syncthreads();     // Rs + V visible to all

        // ---- Phase B: weights + PV accumulation over all 32 keys ----
        {
            const float* ep = Es + n * 1024 + qi;
            const float* rp = Rs + qi;
            u64 wp[16];
#pragma unroll
            for (int j = 0; j < 16; ++j) {
                float w0 = ep[(2 * j + 0) * 32] * rp[(2 * j + 0) * 32];
                float w1 = ep[(2 * j + 1) * 32] * rp[(2 * j + 1) * 32];
                wp[j] = pack2(w0, w1);
            }
            const float* Vb = Vsm + n * 1024;
#pragma unroll 4
            for (int d = 0; d < 32; ++d) {
                const float* vr = Vb + d * 32;
                ulonglong2 vA = *reinterpret_cast<const ulonglong2*>(vr);
                ulonglong2 vB = *reinterpret_cast<const ulonglong2*>(vr + 4);
                ulonglong2 vC = *reinterpret_cast<const ulonglong2*>(vr + 8);
                ulonglong2 vD = *reinterpret_cast<const ulonglong2*>(vr + 12);
                ulonglong2 vE = *reinterpret_cast<const ulonglong2*>(vr + 16);
                ulonglong2 vF = *reinterpret_cast<const ulonglong2*>(vr + 20);
                ulonglong2 vG = *reinterpret_cast<const ulonglong2*>(vr + 24);
                ulonglong2 vH = *reinterpret_cast<const ulonglong2*>(vr + 28);
                fma2(acc[d], wp[0],  vA.x); fma2(acc[d], wp[1],  vA.y);
                fma2(acc[d], wp[2],  vB.x); fma2(acc[d], wp[3],  vB.y);
                fma2(acc[d], wp[4],  vC.x); fma2(acc[d], wp[5],  vC.y);
                fma2(acc[d], wp[6],  vD.x); fma2(acc[d], wp[7],  vD.y);
                fma2(acc[d], wp[8],  vE.x); fma2(acc[d], wp[9],  vE.y);
                fma2(acc[d], wp[10], vF.x); fma2(acc[d], wp[11], vF.y);
                fma2(acc[d], wp[12], vG.x); fma2(acc[d], wp[13], vG.y);
                fma2(acc[d], wp[14], vH.x); fma2(acc[d], wp[15], vH.y);
            }
        }
        // next iteration's top wait+sync orders V/Es reuse
    }

    // ---- write scrambled output: c = n*32 + qt, hw = qi*32 + d ----
    float* orow = attnf + ((size_t)b * 256 + n * 32 + qt) * 1024 + qi * 32;
#pragma unroll
    for (int d4 = 0; d4 < 32; d4 += 4) {
        float2 p0 = unpack2(acc[d4 + 0]);
        float2 p1 = unpack2(acc[d4 + 1]);
        float2 p2 = unpack2(acc[d4 + 2]);
        float2 p3 = unpack2(acc[d4 + 3]);
        *reinterpret_cast<float4*>(orow + d4) =
            make_float4(p0.x + p0.y, p1.x + p1.y, p2.x + p2.y, p3.x + p3.y);
    }
}

// ---------------------------------------------------------------------------
// Launch
// ---------------------------------------------------------------------------
extern "C" void kernel_launch(void* const* d_in, const int* in_sizes, int n_in,
                              void* d_out, int out_size)
{
    (void)in_sizes; (void)n_in; (void)out_size;
    const float* x      = (const float*)d_in[0];   // [8][512][1024]
    const float* w_qkv  = (const float*)d_in[1];   // [768][512]
    const float* b_qkv  = (const float*)d_in[2];   // [768]
    const float* w_attn = (const float*)d_in[3];   // [512][256]
    const float* b_attn = (const float*)d_in[4];   // [512]
    float* out = (float*)d_out;                    // [8][512][1024]

    float *qkv = nullptr, *attnf = nullptr;
    cudaGetSymbolAddress((void**)&qkv, g_qkv);
    cudaGetSymbolAddress((void**)&attnf, g_attnf);

    cudaFuncSetAttribute(attn_kernel,
                         cudaFuncAttributeMaxDynamicSharedMemorySize, 102400);

    // 1) QKV projection + bias, Q rows scaled by 1/sqrt(32)/ln(2)
    gemm_kernel<512, true><<<dim3(8, 6, 8), 256>>>(w_qkv, x, b_qkv, qkv, 768);

    // 2) fused logits / head-softmax(exp2) / PV with output scramble
    attn_kernel<<<dim3(32, 8), 256, 102400>>>(qkv, attnf);

    // 3) output projection + bias
    gemm_kernel<256, false><<<dim3(8, 4, 8), 256>>>(w_attn, attnf, b_attn, out, 512);
}

// round 13
// speedup vs baseline: 1.3656x; 1.1367x over previous
#include <cuda_runtime.h>
#include <cuda_bf16.h>

#define DEV_INLINE __device__ __forceinline__
typedef unsigned long long u64;

// ---------------------------------------------------------------------------
// Packed f32x2 helpers (FFMA2 path — used by attention)
// ---------------------------------------------------------------------------
DEV_INLINE u64 pack2(float x) {
    u64 r;
    asm("mov.b64 %0, {%1, %1};" : "=l"(r) : "r"(__float_as_uint(x)));
    return r;
}
DEV_INLINE u64 pack2(float x, float y) {
    u64 r;
    asm("mov.b64 %0, {%1, %2};" : "=l"(r) : "r"(__float_as_uint(x)), "r"(__float_as_uint(y)));
    return r;
}
DEV_INLINE void fma2(u64& d, u64 a, u64 b) {
    asm("fma.rn.f32x2 %0, %1, %2, %0;" : "+l"(d) : "l"(a), "l"(b));
}
DEV_INLINE float2 unpack2(u64 v) {
    unsigned int lo, hi;
    asm("mov.b64 {%0, %1}, %2;" : "=r"(lo), "=r"(hi) : "l"(v));
    return make_float2(__uint_as_float(lo), __uint_as_float(hi));
}

// base-2 exp via MUFU (single EX2 instruction)
DEV_INLINE float ex2f(float x) {
    float r;
    asm("ex2.approx.f32 %0, %1;" : "=f"(r) : "f"(x));
    return r;
}

// cp.async helpers
DEV_INLINE void cp16(void* dst, const void* src) {
    unsigned d = (unsigned)__cvta_generic_to_shared(dst);
    asm volatile("cp.async.cg.shared.global [%0], [%1], 16;" :: "r"(d), "l"(src) : "memory");
}
DEV_INLINE void cp_commit() { asm volatile("cp.async.commit_group;" ::: "memory"); }
template<int N> DEV_INLINE void cp_wait() { asm volatile("cp.async.wait_group %0;" :: "n"(N) : "memory"); }

// ldmatrix x4 (non-transposed)
DEV_INLINE void ldsm4(unsigned& r0, unsigned& r1, unsigned& r2, unsigned& r3, unsigned addr) {
    asm volatile("ldmatrix.sync.aligned.m8n8.x4.shared.b16 {%0,%1,%2,%3}, [%4];"
        : "=r"(r0), "=r"(r1), "=r"(r2), "=r"(r3) : "r"(addr));
}

// m16n8k16 bf16 MMA, f32 accumulate
DEV_INLINE void mma16816(float* d, const unsigned* a, const unsigned* b) {
    asm volatile("mma.sync.aligned.m16n8k16.row.col.f32.bf16.bf16.f32 "
        "{%0,%1,%2,%3}, {%4,%5,%6,%7}, {%8,%9}, {%0,%1,%2,%3};"
        : "+f"(d[0]), "+f"(d[1]), "+f"(d[2]), "+f"(d[3])
        : "r"(a[0]), "r"(a[1]), "r"(a[2]), "r"(a[3]), "r"(b[0]), "r"(b[1]));
}

// ---------------------------------------------------------------------------
// Scratch (device globals — allocation-free rule)
// ---------------------------------------------------------------------------
__device__ float g_qkv[8 * 768 * 1024];       // [b][o][hw]
__device__ float g_attnf[8 * 256 * 1024];     // scrambled attn output [b][c][hw]
__device__ __nv_bfloat16 g_xT_hi[8 * 1024 * 512];   // x transposed+split [b][hw][c]
__device__ __nv_bfloat16 g_xT_lo[8 * 1024 * 512];
__device__ __nv_bfloat16 g_aT_hi[8 * 1024 * 256];   // attnf transposed+split
__device__ __nv_bfloat16 g_aT_lo[8 * 1024 * 256];
__device__ __nv_bfloat16 g_wq_hi[768 * 512], g_wq_lo[768 * 512];
__device__ __nv_bfloat16 g_wa_hi[512 * 256], g_wa_lo[512 * 256];

// ---------------------------------------------------------------------------
// Elementwise weight split: fp32 -> bf16 hi + bf16 lo (residual)
// ---------------------------------------------------------------------------
__global__ void wsplit_kernel(const float* __restrict__ w,
                              __nv_bfloat16* __restrict__ hi,
                              __nv_bfloat16* __restrict__ lo, int n)
{
    int i = blockIdx.x * 256 + threadIdx.x;
    if (i < n) {
        float v = w[i];
        __nv_bfloat16 h = __float2bfloat16(v);
        hi[i] = h;
        lo[i] = __float2bfloat16(v - __bfloat162float(h));
    }
}

// ---------------------------------------------------------------------------
// Transpose + split: src [b][R][P] fp32 -> dst hi/lo [b][P][R] bf16
// 32x32 tiles, block (32,8)
// ---------------------------------------------------------------------------
__global__ void tsplit_kernel(const float* __restrict__ src,
                              __nv_bfloat16* __restrict__ dhi,
                              __nv_bfloat16* __restrict__ dlo, int R, int P)
{
    __shared__ float t[32][33];
    const int b  = blockIdx.z;
    const int r0 = blockIdx.y * 32;
    const int p0 = blockIdx.x * 32;
    const int tx = threadIdx.x, ty = threadIdx.y;

    const float* s = src + ((size_t)b * R + r0) * P + p0;
#pragma unroll
    for (int i = 0; i < 4; ++i)
        t[ty + i * 8][tx] = s[(size_t)(ty + i * 8) * P + tx];
    __syncthreads();
#pragma unroll
    for (int i = 0; i < 4; ++i) {
        int pr = ty + i * 8;
        float v = t[tx][pr];
        __nv_bfloat16 h = __float2bfloat16(v);
        __nv_bfloat16 l = __float2bfloat16(v - __bfloat162float(h));
        size_t o = ((size_t)b * P + p0 + pr) * R + r0 + tx;
        dhi[o] = h;
        dlo[o] = l;
    }
}

// ---------------------------------------------------------------------------
// Tensor-core GEMM (bf16 split, 3-MMA error compensation):
//   C[b][o][p] = sum_c A[o][c] * B[b][p][c] + bias[o]   (B is K-major!)
// CTA tile 128(o) x 128(p), BK=16, 256 threads = 8 warps (4 o x 2 p),
// warp tile 32x64 = 2x8 m16n8 tiles. Double-buffered cp.async smem.
// Swizzle: 16B chunk index c stored at (c ^ ((row>>2)&1)) -> LDSM conflict-free.
// ---------------------------------------------------------------------------
template<int K_, bool SCALEQ>
__global__ __launch_bounds__(256, 2)
void mma_gemm(const __nv_bfloat16* __restrict__ Ahi, const __nv_bfloat16* __restrict__ Alo,
              const __nv_bfloat16* __restrict__ Bhi, const __nv_bfloat16* __restrict__ Blo,
              const float* __restrict__ bias, float* __restrict__ C, int M)
{
    constexpr int NIT = K_ / 16;
    __shared__ __align__(16) __nv_bfloat16 sA[2][2][128 * 16];  // [stage][hi/lo]
    __shared__ __align__(16) __nv_bfloat16 sB[2][2][128 * 16];

    const int bb = blockIdx.z;
    const int p0 = blockIdx.x * 128;
    const int o0 = blockIdx.y * 128;

    const int tid  = threadIdx.x;
    const int w    = tid >> 5;
    const int lane = tid & 31;
    const int wo   = (w >> 1) * 32;    // warp o-offset
    const int wp   = (w & 1) * 64;     // warp p-offset

    // loader: thread -> (row 0..127, half 0/1); swizzled dst offset (bf16 elems)
    const int ldr  = tid >> 1;
    const int ldh  = tid & 1;
    const int ldoff = ldr * 16 + ((ldh ^ ((ldr >> 2) & 1)) << 3);   // elems
    const __nv_bfloat16* gAhi = Ahi + (size_t)(o0 + ldr) * K_ + ldh * 8;
    const __nv_bfloat16* gAlo = Alo + (size_t)(o0 + ldr) * K_ + ldh * 8;
    const __nv_bfloat16* gBhi = Bhi + ((size_t)bb * 1024 + p0 + ldr) * K_ + ldh * 8;
    const __nv_bfloat16* gBlo = Blo + ((size_t)bb * 1024 + p0 + ldr) * K_ + ldh * 8;

    // LDSM per-thread byte offsets (within one 128x16 array)
    const int lm = lane >> 3, lr = lane & 7;
    unsigned aoff[2], boff[4];
#pragma unroll
    for (int mt = 0; mt < 2; ++mt) {
        int row = wo + mt * 16 + (lm & 1) * 8 + lr;
        int ch  = lm >> 1;
        aoff[mt] = row * 32 + ((ch ^ ((row >> 2) & 1)) << 4);
    }
#pragma unroll
    for (int nt2 = 0; nt2 < 4; ++nt2) {
        int row = wp + nt2 * 16 + (lm >> 1) * 8 + lr;
        int ch  = lm & 1;
        boff[nt2] = row * 32 + ((ch ^ ((row >> 2) & 1)) << 4);
    }
    const unsigned sAaddr = (unsigned)__cvta_generic_to_shared(&sA[0][0][0]);
    const unsigned sBaddr = (unsigned)__cvta_generic_to_shared(&sB[0][0][0]);

    float acc[2][8][4];
#pragma unroll
    for (int i = 0; i < 2; ++i)
#pragma unroll
        for (int j = 0; j < 8; ++j)
#pragma unroll
            for (int k = 0; k < 4; ++k) acc[i][j][k] = 0.0f;

    // prologue: stage 0
    {
        cp16(&sA[0][0][ldoff], gAhi);
        cp16(&sA[0][1][ldoff], gAlo);
        cp16(&sB[0][0][ldoff], gBhi);
        cp16(&sB[0][1][ldoff], gBlo);
        cp_commit();
    }

    for (int it = 0; it < NIT; ++it) {
        const int st = it & 1;
        if (it + 1 < NIT) {
            const int ns = st ^ 1;
            const int c1 = (it + 1) * 16;
            cp16(&sA[ns][0][ldoff], gAhi + c1);
            cp16(&sA[ns][1][ldoff], gAlo + c1);
            cp16(&sB[ns][0][ldoff], gBhi + c1);
            cp16(&sB[ns][1][ldoff], gBlo + c1);
            cp_commit();
            cp_wait<1>();
        } else {
            cp_wait<0>();
        }
        __syncthreads();

        const unsigned aBase = sAaddr + st * 8192;   // bytes: [st][hl] hl stride 4096
        const unsigned bBase = sBaddr + st * 8192;

        unsigned ah[2][4], al[2][4], bh[4][4], bl[4][4];
#pragma unroll
        for (int mt = 0; mt < 2; ++mt) {
            ldsm4(ah[mt][0], ah[mt][1], ah[mt][2], ah[mt][3], aBase + aoff[mt]);
            ldsm4(al[mt][0], al[mt][1], al[mt][2], al[mt][3], aBase + 4096 + aoff[mt]);
        }
#pragma unroll
        for (int nt2 = 0; nt2 < 4; ++nt2) {
            ldsm4(bh[nt2][0], bh[nt2][1], bh[nt2][2], bh[nt2][3], bBase + boff[nt2]);
            ldsm4(bl[nt2][0], bl[nt2][1], bl[nt2][2], bl[nt2][3], bBase + 4096 + boff[nt2]);
        }

#pragma unroll
        for (int mt = 0; mt < 2; ++mt)
#pragma unroll
            for (int nt2 = 0; nt2 < 4; ++nt2)
#pragma unroll
                for (int sub = 0; sub < 2; ++sub) {
                    float* d = acc[mt][nt2 * 2 + sub];
                    mma16816(d, ah[mt], &bh[nt2][sub * 2]);   // hi*hi
                    mma16816(d, ah[mt], &bl[nt2][sub * 2]);   // hi*lo
                    mma16816(d, al[mt], &bh[nt2][sub * 2]);   // lo*hi
                }
        __syncthreads();
    }

    // epilogue: bias (+ Q scale incl. 1/ln2 for exp2 softmax), fp32 store
    constexpr float QSC = 0.17677669529663687f * 1.4426950408889634f;
    const int er = lane >> 2, ec = (lane & 3) * 2;
#pragma unroll
    for (int mt = 0; mt < 2; ++mt) {
        const int o1 = o0 + wo + mt * 16 + er;
        const int o2 = o1 + 8;
        const float bv1 = bias[o1];
        const float bv2 = bias[o2];
        const float s1 = (SCALEQ && o1 < 256) ? QSC : 1.0f;
        const float s2 = (SCALEQ && o2 < 256) ? QSC : 1.0f;
#pragma unroll
        for (int nt = 0; nt < 8; ++nt) {
            const int p = p0 + wp + nt * 8 + ec;
            float* c1 = C + ((size_t)bb * M + o1) * 1024 + p;
            float* c2 = C + ((size_t)bb * M + o2) * 1024 + p;
            const float* a = acc[mt][nt];
            *reinterpret_cast<float2*>(c1) = make_float2((a[0] + bv1) * s1, (a[1] + bv1) * s1);
            *reinterpret_cast<float2*>(c2) = make_float2((a[2] + bv2) * s2, (a[3] + bv2) * s2);
        }
    }
}

// ---------------------------------------------------------------------------
// Fused attention v5 (UNCHANGED from R12 — 561us-passing version).
// Grid: (q_tile=32, b=8); 256 threads = 8 warps (warp = head). 2 CTAs/SM.
// smem floats: K[256][32] | V[256][32] | Es[8][32][32] | Rs[32][32] = 100 KB.
// ---------------------------------------------------------------------------
__global__ __launch_bounds__(256, 2)
void attn_kernel(const float* __restrict__ qkv, float* __restrict__ attnf)
{
    extern __shared__ float sm[];
    float* Ksm = sm;              // [256][32]  row = n*32+d
    float* Vsm = sm + 8192;       // [256][32]
    float* Es  = sm + 16384;      // [8][32][32] = [n][k][qi]
    float* Rs  = sm + 24576;      // [32][32]    = [k][qi]

    const int b  = blockIdx.y;
    const int qt = blockIdx.x;
    const int q0 = qt * 32;
    const float* QKV = qkv + (size_t)b * 768 * 1024;

    const int tid = threadIdx.x;
    const int n   = tid >> 5;
    const int qi  = tid & 31;

    const int lr = tid >> 3;
    const int lc = (tid & 7) * 4;

#pragma unroll
    for (int c = 0; c < 8; ++c) {
        int r = lr + c * 32;
        cp16(&Ksm[r * 32 + lc], QKV + (size_t)(256 + r) * 1024 + 0 + lc);
    }
    cp_commit();

    u64 acc[32];
#pragma unroll
    for (int d = 0; d < 32; ++d) acc[d] = 0ull;

    const float* Qg = QKV + (size_t)(n * 32) * 1024 + q0 + qi;

    for (int kt = 0; kt < 32; ++kt) {
        cp_wait<0>();
        __syncthreads();

        {
            const int k0 = kt * 32;
#pragma unroll
            for (int c = 0; c < 8; ++c) {
                int r = lr + c * 32;
                cp16(&Vsm[r * 32 + lc], QKV + (size_t)(512 + r) * 1024 + k0 + lc);
            }
            cp_commit();
        }

        {
            const float* Kb = Ksm + n * 1024;
            u64 l2[16];
#pragma unroll
            for (int p = 0; p < 16; ++p) l2[p] = 0ull;
#pragma unroll 4
            for (int d = 0; d < 32; ++d) {
                u64 qq = pack2(Qg[d * 1024]);
                const float* kr = Kb + d * 32;
                ulonglong2 kA = *reinterpret_cast<const ulonglong2*>(kr);
                ulonglong2 kB = *reinterpret_cast<const ulonglong2*>(kr + 4);
                ulonglong2 kC = *reinterpret_cast<const ulonglong2*>(kr + 8);
                ulonglong2 kD = *reinterpret_cast<const ulonglong2*>(kr + 12);
                ulonglong2 kE = *reinterpret_cast<const ulonglong2*>(kr + 16);
                ulonglong2 kF = *reinterpret_cast<const ulonglong2*>(kr + 20);
                ulonglong2 kG = *reinterpret_cast<const ulonglong2*>(kr + 24);
                ulonglong2 kH = *reinterpret_cast<const ulonglong2*>(kr + 28);
                fma2(l2[0],  qq, kA.x); fma2(l2[1],  qq, kA.y);
                fma2(l2[2],  qq, kB.x); fma2(l2[3],  qq, kB.y);
                fma2(l2[4],  qq, kC.x); fma2(l2[5],  qq, kC.y);
                fma2(l2[6],  qq, kD.x); fma2(l2[7],  qq, kD.y);
                fma2(l2[8],  qq, kE.x); fma2(l2[9],  qq, kE.y);
                fma2(l2[10], qq, kF.x); fma2(l2[11], qq, kF.y);
                fma2(l2[12], qq, kG.x); fma2(l2[13], qq, kG.y);
                fma2(l2[14], qq, kH.x); fma2(l2[15], qq, kH.y);
            }
            float* eb = Es + n * 1024 + qi;
#pragma unroll
            for (int p = 0; p < 16; ++p) {
                float2 lv = unpack2(l2[p]);
                eb[(2 * p + 0) * 32] = ex2f(lv.x);
                eb[(2 * p + 1) * 32] = ex2f(lv.y);
            }
        }
        __syncthreads();

        {
            const int k0n = (kt + 1 < 32) ? (kt + 1) * 32 : 0;
#pragma unroll
            for (int c = 0; c < 8; ++c) {
                int r = lr + c * 32;
                cp16(&Ksm[r * 32 + lc], QKV + (size_t)(256 + r) * 1024 + k0n + lc);
            }
            cp_commit();
        }

#pragma unroll
        for (int pp = 0; pp < 4; ++pp) {
            int p = tid + pp * 256;
            float s = Es[p] + Es[1024 + p] + Es[2048 + p] + Es[3072 + p]
                    + Es[4096 + p] + Es[5120 + p] + Es[6144 + p] + Es[7168 + p];
            Rs[p] = __fdividef(1.0f, s);
        }
        cp_wait<1>();
        __syncthreads();

        {
            const float* ep = Es + n * 1024 + qi;
            const float* rp = Rs + qi;
            u64 wp[16];
#pragma unroll
            for (int j = 0; j < 16; ++j) {
                float w0 = ep[(2 * j + 0) * 32] * rp[(2 * j + 0) * 32];
                float w1 = ep[(2 * j + 1) * 32] * rp[(2 * j + 1) * 32];
                wp[j] = pack2(w0, w1);
            }
            const float* Vb = Vsm + n * 1024;
#pragma unroll 4
            for (int d = 0; d < 32; ++d) {
                const float* vr = Vb + d * 32;
                ulonglong2 vA = *reinterpret_cast<const ulonglong2*>(vr);
                ulonglong2 vB = *reinterpret_cast<const ulonglong2*>(vr + 4);
                ulonglong2 vC = *reinterpret_cast<const ulonglong2*>(vr + 8);
                ulonglong2 vD = *reinterpret_cast<const ulonglong2*>(vr + 12);
                ulonglong2 vE = *reinterpret_cast<const ulonglong2*>(vr + 16);
                ulonglong2 vF = *reinterpret_cast<const ulonglong2*>(vr + 20);
                ulonglong2 vG = *reinterpret_cast<const ulonglong2*>(vr + 24);
                ulonglong2 vH = *reinterpret_cast<const ulonglong2*>(vr + 28);
                fma2(acc[d], wp[0],  vA.x); fma2(acc[d], wp[1],  vA.y);
                fma2(acc[d], wp[2],  vB.x); fma2(acc[d], wp[3],  vB.y);
                fma2(acc[d], wp[4],  vC.x); fma2(acc[d], wp[5],  vC.y);
                fma2(acc[d], wp[6],  vD.x); fma2(acc[d], wp[7],  vD.y);
                fma2(acc[d], wp[8],  vE.x); fma2(acc[d], wp[9],  vE.y);
                fma2(acc[d], wp[10], vF.x); fma2(acc[d], wp[11], vF.y);
                fma2(acc[d], wp[12], vG.x); fma2(acc[d], wp[13], vG.y);
                fma2(acc[d], wp[14], vH.x); fma2(acc[d], wp[15], vH.y);
            }
        }
    }

    float* orow = attnf + ((size_t)b * 256 + n * 32 + qt) * 1024 + qi * 32;
#pragma unroll
    for (int d4 = 0; d4 < 32; d4 += 4) {
        float2 p0 = unpack2(acc[d4 + 0]);
        float2 p1 = unpack2(acc[d4 + 1]);
        float2 p2 = unpack2(acc[d4 + 2]);
        float2 p3 = unpack2(acc[d4 + 3]);
        *reinterpret_cast<float4*>(orow + d4) =
            make_float4(p0.x + p0.y, p1.x + p1.y, p2.x + p2.y, p3.x + p3.y);
    }
}

// ---------------------------------------------------------------------------
// Launch
// ---------------------------------------------------------------------------
extern "C" void kernel_launch(void* const* d_in, const int* in_sizes, int n_in,
                              void* d_out, int out_size)
{
    (void)in_sizes; (void)n_in; (void)out_size;
    const float* x      = (const float*)d_in[0];   // [8][512][1024]
    const float* w_qkv  = (const float*)d_in[1];   // [768][512]
    const float* b_qkv  = (const float*)d_in[2];   // [768]
    const float* w_attn = (const float*)d_in[3];   // [512][256]
    const float* b_attn = (const float*)d_in[4];   // [512]
    float* out = (float*)d_out;                    // [8][512][1024]

    float *qkv = nullptr, *attnf = nullptr;
    __nv_bfloat16 *xh, *xl, *ah, *al, *wqh, *wql, *wah, *wal;
    cudaGetSymbolAddress((void**)&qkv, g_qkv);
    cudaGetSymbolAddress((void**)&attnf, g_attnf);
    cudaGetSymbolAddress((void**)&xh, g_xT_hi);
    cudaGetSymbolAddress((void**)&xl, g_xT_lo);
    cudaGetSymbolAddress((void**)&ah, g_aT_hi);
    cudaGetSymbolAddress((void**)&al, g_aT_lo);
    cudaGetSymbolAddress((void**)&wqh, g_wq_hi);
    cudaGetSymbolAddress((void**)&wql, g_wq_lo);
    cudaGetSymbolAddress((void**)&wah, g_wa_hi);
    cudaGetSymbolAddress((void**)&wal, g_wa_lo);

    cudaFuncSetAttribute(attn_kernel,
                         cudaFuncAttributeMaxDynamicSharedMemorySize, 102400);

    // 0) split weights to bf16 hi/lo
    wsplit_kernel<<<(768 * 512 + 255) / 256, 256>>>(w_qkv, wqh, wql, 768 * 512);
    wsplit_kernel<<<(512 * 256 + 255) / 256, 256>>>(w_attn, wah, wal, 512 * 256);

    // 0b) transpose + split x -> [b][hw][c] bf16 hi/lo
    tsplit_kernel<<<dim3(32, 16, 8), dim3(32, 8)>>>(x, xh, xl, 512, 1024);

    // 1) QKV projection (tensor core, 3-MMA split) + bias, Q scaled 1/sqrt(32)/ln2
    mma_gemm<512, true><<<dim3(8, 6, 8), 256>>>(wqh, wql, xh, xl, b_qkv, qkv, 768);

    // 2) fused logits / head-softmax(exp2) / PV with output scramble
    attn_kernel<<<dim3(32, 8), 256, 102400>>>(qkv, attnf);

    // 2b) transpose + split attn output -> [b][hw][c] bf16 hi/lo
    tsplit_kernel<<<dim3(32, 8, 8), dim3(32, 8)>>>(attnf, ah, al, 256, 1024);

    // 3) output projection (tensor core) + bias
    mma_gemm<256, false><<<dim3(8, 4, 8), 256>>>(wah, wal, ah, al, b_attn, out, 512);
}

// round 14
// speedup vs baseline: 2.8573x; 2.0924x over previous
#include <cuda_runtime.h>
#include <cuda_bf16.h>

#define DEV_INLINE __device__ __forceinline__

// base-2 exp via MUFU (single EX2 instruction)
DEV_INLINE float ex2f(float x) {
    float r;
    asm("ex2.approx.f32 %0, %1;" : "=f"(r) : "f"(x));
    return r;
}

// cp.async helpers
DEV_INLINE void cp16(void* dst, const void* src) {
    unsigned d = (unsigned)__cvta_generic_to_shared(dst);
    asm volatile("cp.async.cg.shared.global [%0], [%1], 16;" :: "r"(d), "l"(src) : "memory");
}
DEV_INLINE void cp_commit() { asm volatile("cp.async.commit_group;" ::: "memory"); }
template<int N> DEV_INLINE void cp_wait() { asm volatile("cp.async.wait_group %0;" :: "n"(N) : "memory"); }

// ldmatrix x4 (non-transposed)
DEV_INLINE void ldsm4(unsigned& r0, unsigned& r1, unsigned& r2, unsigned& r3, unsigned addr) {
    asm volatile("ldmatrix.sync.aligned.m8n8.x4.shared.b16 {%0,%1,%2,%3}, [%4];"
        : "=r"(r0), "=r"(r1), "=r"(r2), "=r"(r3) : "r"(addr));
}

// m16n8k16 bf16 MMA, f32 accumulate
DEV_INLINE void mma16816(float* d, const unsigned* a, const unsigned* b) {
    asm volatile("mma.sync.aligned.m16n8k16.row.col.f32.bf16.bf16.f32 "
        "{%0,%1,%2,%3}, {%4,%5,%6,%7}, {%8,%9}, {%0,%1,%2,%3};"
        : "+f"(d[0]), "+f"(d[1]), "+f"(d[2]), "+f"(d[3])
        : "r"(a[0]), "r"(a[1]), "r"(a[2]), "r"(a[3]), "r"(b[0]), "r"(b[1]));
}

// pack two f32 -> bf16x2 {lo = a (first k elem), hi = b}
DEV_INLINE unsigned packbf(float a, float b) {
    unsigned r;
    asm("cvt.rn.bf16x2.f32 %0, %1, %2;" : "=r"(r) : "f"(b), "f"(a));
    return r;
}
DEV_INLINE float bflo(unsigned p) { return __uint_as_float(p << 16); }
DEV_INLINE float bfhi(unsigned p) { return __uint_as_float(p & 0xffff0000u); }

// non-coherent 4B global load, volatile so it isn't hoisted out of the kt loop
DEV_INLINE void ldg32(unsigned& r, const __nv_bfloat16* p) {
    asm volatile("ld.global.nc.u32 %0, [%1];" : "=r"(r) : "l"(p));
}

// ---------------------------------------------------------------------------
// Scratch (device globals — allocation-free rule)
// ---------------------------------------------------------------------------
__device__ float g_qkv[8 * 768 * 1024];       // [b][o][hw]
__device__ float g_attnf[8 * 256 * 1024];     // scrambled attn output [b][c][hw]
__device__ __nv_bfloat16 g_xT_hi[8 * 1024 * 512];   // x transposed+split [b][hw][c]
__device__ __nv_bfloat16 g_xT_lo[8 * 1024 * 512];
__device__ __nv_bfloat16 g_aT_hi[8 * 1024 * 256];   // attnf transposed+split
__device__ __nv_bfloat16 g_aT_lo[8 * 1024 * 256];
__device__ __nv_bfloat16 g_wq_hi[768 * 512], g_wq_lo[768 * 512];
__device__ __nv_bfloat16 g_wa_hi[512 * 256], g_wa_lo[512 * 256];
// attention operands, bf16 split
__device__ __nv_bfloat16 g_qT_hi[8 * 8 * 1024 * 32], g_qT_lo[8 * 8 * 1024 * 32]; // [b][n][q][d]
__device__ __nv_bfloat16 g_kT_hi[8 * 8 * 1024 * 32], g_kT_lo[8 * 8 * 1024 * 32]; // [b][n][k][d]
__device__ __nv_bfloat16 g_v_hi [8 * 8 * 32 * 1024], g_v_lo [8 * 8 * 32 * 1024]; // [b][n][d][k]

// ---------------------------------------------------------------------------
// Elementwise weight split: fp32 -> bf16 hi + bf16 lo (residual)
// ---------------------------------------------------------------------------
__global__ void wsplit_kernel(const float* __restrict__ w,
                              __nv_bfloat16* __restrict__ hi,
                              __nv_bfloat16* __restrict__ lo, int n)
{
    int i = blockIdx.x * 256 + threadIdx.x;
    if (i < n) {
        float v = w[i];
        __nv_bfloat16 h = __float2bfloat16(v);
        hi[i] = h;
        lo[i] = __float2bfloat16(v - __bfloat162float(h));
    }
}

// ---------------------------------------------------------------------------
// Transpose + split: src [b][R][P] fp32 -> dst hi/lo [b][P][R] bf16
// ---------------------------------------------------------------------------
__global__ void tsplit_kernel(const float* __restrict__ src,
                              __nv_bfloat16* __restrict__ dhi,
                              __nv_bfloat16* __restrict__ dlo, int R, int P)
{
    __shared__ float t[32][33];
    const int b  = blockIdx.z;
    const int r0 = blockIdx.y * 32;
    const int p0 = blockIdx.x * 32;
    const int tx = threadIdx.x, ty = threadIdx.y;

    const float* s = src + ((size_t)b * R + r0) * P + p0;
#pragma unroll
    for (int i = 0; i < 4; ++i)
        t[ty + i * 8][tx] = s[(size_t)(ty + i * 8) * P + tx];
    __syncthreads();
#pragma unroll
    for (int i = 0; i < 4; ++i) {
        int pr = ty + i * 8;
        float v = t[tx][pr];
        __nv_bfloat16 h = __float2bfloat16(v);
        __nv_bfloat16 l = __float2bfloat16(v - __bfloat162float(h));
        size_t o = ((size_t)b * P + p0 + pr) * R + r0 + tx;
        dhi[o] = h;
        dlo[o] = l;
    }
}

// ---------------------------------------------------------------------------
// Prep: from qkv fp32 build attention operands (bf16 hi/lo)
//   Q part -> qT [b][n][q][d] (transposed per head), K -> kT likewise,
//   V -> v [b][n][d][k] (straight convert).
// grid (32 hw-tiles, 24 = 3types x 8heads, 8 b), block (32,8)
// ---------------------------------------------------------------------------
__global__ void prep_kernel(const float* __restrict__ qkv,
                            __nv_bfloat16* __restrict__ qTh, __nv_bfloat16* __restrict__ qTl,
                            __nv_bfloat16* __restrict__ kTh, __nv_bfloat16* __restrict__ kTl,
                            __nv_bfloat16* __restrict__ vh,  __nv_bfloat16* __restrict__ vl)
{
    __shared__ float sm[32][33];
    const int b   = blockIdx.z;
    const int typ = blockIdx.y >> 3;   // 0 Q, 1 K, 2 V
    const int n   = blockIdx.y & 7;
    const int tt  = blockIdx.x;
    const int tx = threadIdx.x, ty = threadIdx.y;
    const float* in = qkv + ((size_t)b * 768 + typ * 256 + n * 32) * 1024 + (size_t)tt * 32;
    const size_t hb = (size_t)(b * 8 + n);

    if (typ == 2) {
#pragma unroll
        for (int i = 0; i < 4; ++i) {
            int d = ty + i * 8;
            float v = in[(size_t)d * 1024 + tx];
            __nv_bfloat16 h = __float2bfloat16(v);
            size_t o = (hb * 32 + d) * 1024 + (size_t)tt * 32 + tx;
            vh[o] = h;
            vl[o] = __float2bfloat16(v - __bfloat162float(h));
        }
    } else {
#pragma unroll
        for (int i = 0; i < 4; ++i)
            sm[ty + i * 8][tx] = in[(size_t)(ty + i * 8) * 1024 + tx];
        __syncthreads();
        __nv_bfloat16* oh = (typ ? kTh : qTh) + (hb * 1024 + (size_t)tt * 32) * 32;
        __nv_bfloat16* ol = (typ ? kTl : qTl) + (hb * 1024 + (size_t)tt * 32) * 32;
#pragma unroll
        for (int i = 0; i < 4; ++i) {
            int q = ty + i * 8;
            float v = sm[tx][q];
            __nv_bfloat16 h = __float2bfloat16(v);
            oh[q * 32 + tx] = h;
            ol[q * 32 + tx] = __float2bfloat16(v - __bfloat162float(h));
        }
    }
}

// ---------------------------------------------------------------------------
// Tensor-core GEMM (bf16 split, 3-MMA) — unchanged from R13 (passing, 70us).
// ---------------------------------------------------------------------------
template<int K_, bool SCALEQ>
__global__ __launch_bounds__(256, 2)
void mma_gemm(const __nv_bfloat16* __restrict__ Ahi, const __nv_bfloat16* __restrict__ Alo,
              const __nv_bfloat16* __restrict__ Bhi, const __nv_bfloat16* __restrict__ Blo,
              const float* __restrict__ bias, float* __restrict__ C, int M)
{
    constexpr int NIT = K_ / 16;
    __shared__ __align__(16) __nv_bfloat16 sA[2][2][128 * 16];
    __shared__ __align__(16) __nv_bfloat16 sB[2][2][128 * 16];

    const int bb = blockIdx.z;
    const int p0 = blockIdx.x * 128;
    const int o0 = blockIdx.y * 128;

    const int tid  = threadIdx.x;
    const int w    = tid >> 5;
    const int lane = tid & 31;
    const int wo   = (w >> 1) * 32;
    const int wp   = (w & 1) * 64;

    const int ldr  = tid >> 1;
    const int ldh  = tid & 1;
    const int ldoff = ldr * 16 + ((ldh ^ ((ldr >> 2) & 1)) << 3);
    const __nv_bfloat16* gAhi = Ahi + (size_t)(o0 + ldr) * K_ + ldh * 8;
    const __nv_bfloat16* gAlo = Alo + (size_t)(o0 + ldr) * K_ + ldh * 8;
    const __nv_bfloat16* gBhi = Bhi + ((size_t)bb * 1024 + p0 + ldr) * K_ + ldh * 8;
    const __nv_bfloat16* gBlo = Blo + ((size_t)bb * 1024 + p0 + ldr) * K_ + ldh * 8;

    const int lm = lane >> 3, lr = lane & 7;
    unsigned aoff[2], boff[4];
#pragma unroll
    for (int mt = 0; mt < 2; ++mt) {
        int row = wo + mt * 16 + (lm & 1) * 8 + lr;
        int ch  = lm >> 1;
        aoff[mt] = row * 32 + ((ch ^ ((row >> 2) & 1)) << 4);
    }
#pragma unroll
    for (int nt2 = 0; nt2 < 4; ++nt2) {
        int row = wp + nt2 * 16 + (lm >> 1) * 8 + lr;
        int ch  = lm & 1;
        boff[nt2] = row * 32 + ((ch ^ ((row >> 2) & 1)) << 4);
    }
    const unsigned sAaddr = (unsigned)__cvta_generic_to_shared(&sA[0][0][0]);
    const unsigned sBaddr = (unsigned)__cvta_generic_to_shared(&sB[0][0][0]);

    float acc[2][8][4];
#pragma unroll
    for (int i = 0; i < 2; ++i)
#pragma unroll
        for (int j = 0; j < 8; ++j)
#pragma unroll
            for (int k = 0; k < 4; ++k) acc[i][j][k] = 0.0f;

    cp16(&sA[0][0][ldoff], gAhi);
    cp16(&sA[0][1][ldoff], gAlo);
    cp16(&sB[0][0][ldoff], gBhi);
    cp16(&sB[0][1][ldoff], gBlo);
    cp_commit();

    for (int it = 0; it < NIT; ++it) {
        const int st = it & 1;
        if (it + 1 < NIT) {
            const int ns = st ^ 1;
            const int c1 = (it + 1) * 16;
            cp16(&sA[ns][0][ldoff], gAhi + c1);
            cp16(&sA[ns][1][ldoff], gAlo + c1);
            cp16(&sB[ns][0][ldoff], gBhi + c1);
            cp16(&sB[ns][1][ldoff], gBlo + c1);
            cp_commit();
            cp_wait<1>();
        } else {
            cp_wait<0>();
        }
        __syncthreads();

        const unsigned aBase = sAaddr + st * 8192;
        const unsigned bBase = sBaddr + st * 8192;

        unsigned ah[2][4], al[2][4], bh[4][4], bl[4][4];
#pragma unroll
        for (int mt = 0; mt < 2; ++mt) {
            ldsm4(ah[mt][0], ah[mt][1], ah[mt][2], ah[mt][3], aBase + aoff[mt]);
            ldsm4(al[mt][0], al[mt][1], al[mt][2], al[mt][3], aBase + 4096 + aoff[mt]);
        }
#pragma unroll
        for (int nt2 = 0; nt2 < 4; ++nt2) {
            ldsm4(bh[nt2][0], bh[nt2][1], bh[nt2][2], bh[nt2][3], bBase + boff[nt2]);
            ldsm4(bl[nt2][0], bl[nt2][1], bl[nt2][2], bl[nt2][3], bBase + 4096 + boff[nt2]);
        }

#pragma unroll
        for (int mt = 0; mt < 2; ++mt)
#pragma unroll
            for (int nt2 = 0; nt2 < 4; ++nt2)
#pragma unroll
                for (int sub = 0; sub < 2; ++sub) {
                    float* d = acc[mt][nt2 * 2 + sub];
                    mma16816(d, ah[mt], &bh[nt2][sub * 2]);
                    mma16816(d, ah[mt], &bl[nt2][sub * 2]);
                    mma16816(d, al[mt], &bh[nt2][sub * 2]);
                }
        __syncthreads();
    }

    constexpr float QSC = 0.17677669529663687f * 1.4426950408889634f;
    const int er = lane >> 2, ec = (lane & 3) * 2;
#pragma unroll
    for (int mt = 0; mt < 2; ++mt) {
        const int o1 = o0 + wo + mt * 16 + er;
        const int o2 = o1 + 8;
        const float bv1 = bias[o1];
        const float bv2 = bias[o2];
        const float s1 = (SCALEQ && o1 < 256) ? QSC : 1.0f;
        const float s2 = (SCALEQ && o2 < 256) ? QSC : 1.0f;
#pragma unroll
        for (int nt = 0; nt < 8; ++nt) {
            const int p = p0 + wp + nt * 8 + ec;
            float* c1 = C + ((size_t)bb * M + o1) * 1024 + p;
            float* c2 = C + ((size_t)bb * M + o2) * 1024 + p;
            const float* a = acc[mt][nt];
            *reinterpret_cast<float2*>(c1) = make_float2((a[0] + bv1) * s1, (a[1] + bv1) * s1);
            *reinterpret_cast<float2*>(c2) = make_float2((a[2] + bv2) * s2, (a[3] + bv2) * s2);
        }
    }
}

// ---------------------------------------------------------------------------
// Tensor-core fused attention. Grid (32 qt, 8 b); 256 thr = 8 warps (warp=head).
// Per kt (32 keys): S = Qt*Kt^T via 3-split bf16 MMA; exp2 on C-frags; Es/Rs
// head-sum exchange (XOR-swizzled); W = e*r packed in-register to bf16 hi/lo
// A-frags (C-frag == A-frag layout identity); PV via 3-split MMA with V B-frags.
// smem bytes: Khi 16K | Klo 16K | Vhi 16K | Vlo 16K | Es 32K | Rs 4K = 100 KB.
// ---------------------------------------------------------------------------
__global__ __launch_bounds__(256, 2)
void attn_mma_kernel(const __nv_bfloat16* __restrict__ qTh, const __nv_bfloat16* __restrict__ qTl,
                     const __nv_bfloat16* __restrict__ kTh, const __nv_bfloat16* __restrict__ kTl,
                     const __nv_bfloat16* __restrict__ vh,  const __nv_bfloat16* __restrict__ vl,
                     float* __restrict__ attnf)
{
    extern __shared__ char smc[];
    float* Es = (float*)(smc + 65536);   // [8][32][32] = [n][q][k-slot]
    float* Rs = (float*)(smc + 98304);   // [32][32]    = [q][k-slot]

    const int b   = blockIdx.y;
    const int qt  = blockIdx.x;
    const int tid = threadIdx.x;
    const int n = tid >> 5, lane = tid & 31;
    const int g = lane >> 2, t = lane & 3;
    const int lm = lane >> 3, lr = lane & 7;

    // ---- loader precompute: 4 chunks each for K-hi/lo and V-hi/lo ----
    int dstKV[4];
    const __nv_bfloat16 *sKh[4], *sKl[4], *sVh[4], *sVl[4];
#pragma unroll
    for (int c = 0; c < 4; ++c) {
        int i = tid + c * 256;
        int nn = i >> 7, rr = (i >> 2) & 31, ch = i & 3;
        dstKV[c] = nn * 2048 + rr * 64 + ((ch ^ ((rr >> 1) & 3)) << 4);
        size_t hb = (size_t)(b * 8 + nn);
        sKh[c] = kTh + (hb * 1024 + rr) * 32 + ch * 8;
        sKl[c] = kTl + (hb * 1024 + rr) * 32 + ch * 8;
        sVh[c] = vh + (hb * 32 + rr) * 1024 + ch * 8;
        sVl[c] = vl + (hb * 32 + rr) * 1024 + ch * 8;
    }

    // ldsm frag byte-offsets within a 32x32 bf16 tile (64B rows, XOR swizzle)
    int ldo[2][2];
#pragma unroll
    for (int grp = 0; grp < 2; ++grp)
#pragma unroll
        for (int j = 0; j < 2; ++j) {
            int row = grp * 16 + ((lm >> 1) << 3) + lr;
            int ch  = j * 2 + (lm & 1);
            ldo[grp][j] = row * 64 + ((ch ^ ((row >> 1) & 3)) << 4);
        }

    const unsigned sb  = (unsigned)__cvta_generic_to_shared(smc);
    const unsigned bKh = sb + n * 2048;
    const unsigned bKl = bKh + 16384;
    const unsigned bVh = bKh + 32768;
    const unsigned bVl = bKh + 49152;

    const __nv_bfloat16* qbh = qTh + ((size_t)(b * 8 + n) * 1024 + (size_t)qt * 32) * 32;
    const __nv_bfloat16* qbl = qTl + ((size_t)(b * 8 + n) * 1024 + (size_t)qt * 32) * 32;

    float out[2][4][4];
#pragma unroll
    for (int i = 0; i < 2; ++i)
#pragma unroll
        for (int j = 0; j < 4; ++j)
#pragma unroll
            for (int k = 0; k < 4; ++k) out[i][j][k] = 0.0f;

    // prologue: K(0)
#pragma unroll
    for (int c = 0; c < 4; ++c) {
        cp16(smc + dstKV[c], sKh[c]);
        cp16(smc + 16384 + dstKV[c], sKl[c]);
    }
    cp_commit();

    for (int kt = 0; kt < 32; ++kt) {
        cp_wait<0>();
        __syncthreads();   // K(kt) visible; all warps past phase B(kt-1)

        // issue V(kt) — lands during phase A
#pragma unroll
        for (int c = 0; c < 4; ++c) {
            cp16(smc + 32768 + dstKV[c], sVh[c] + kt * 32);
            cp16(smc + 49152 + dstKV[c], sVl[c] + kt * 32);
        }
        cp_commit();

        // ---- Phase A: S = Q*K^T (3-split), exp2, publish Es ----
        unsigned kh[2][2][4], kl[2][2][4];
#pragma unroll
        for (int grp = 0; grp < 2; ++grp)
#pragma unroll
            for (int j = 0; j < 2; ++j) {
                ldsm4(kh[grp][j][0], kh[grp][j][1], kh[grp][j][2], kh[grp][j][3], bKh + ldo[grp][j]);
                ldsm4(kl[grp][j][0], kl[grp][j][1], kl[grp][j][2], kl[grp][j][3], bKl + ldo[grp][j]);
            }
        unsigned qh[2][2][4], ql[2][2][4];
#pragma unroll
        for (int mt = 0; mt < 2; ++mt)
#pragma unroll
            for (int j = 0; j < 2; ++j) {
                int r0 = (mt * 16 + g) * 32 + j * 16 + t * 2;
                ldg32(qh[mt][j][0], qbh + r0);
                ldg32(qh[mt][j][1], qbh + r0 + 256);
                ldg32(qh[mt][j][2], qbh + r0 + 8);
                ldg32(qh[mt][j][3], qbh + r0 + 264);
                ldg32(ql[mt][j][0], qbl + r0);
                ldg32(ql[mt][j][1], qbl + r0 + 256);
                ldg32(ql[mt][j][2], qbl + r0 + 8);
                ldg32(ql[mt][j][3], qbl + r0 + 264);
            }
        float S[2][4][4];
#pragma unroll
        for (int i = 0; i < 2; ++i)
#pragma unroll
            for (int j = 0; j < 4; ++j)
#pragma unroll
                for (int k = 0; k < 4; ++k) S[i][j][k] = 0.0f;
#pragma unroll
        for (int mt = 0; mt < 2; ++mt)
#pragma unroll
            for (int kg = 0; kg < 2; ++kg)
#pragma unroll
                for (int sub = 0; sub < 2; ++sub) {
                    float* d = S[mt][kg * 2 + sub];
#pragma unroll
                    for (int j = 0; j < 2; ++j) {
                        mma16816(d, qh[mt][j], &kh[kg][j][sub * 2]);
                        mma16816(d, qh[mt][j], &kl[kg][j][sub * 2]);
                        mma16816(d, ql[mt][j], &kh[kg][j][sub * 2]);
                    }
                }
        float e[2][4][4];
#pragma unroll
        for (int mt = 0; mt < 2; ++mt) {
            int q = mt * 16 + g;
#pragma unroll
            for (int nt = 0; nt < 4; ++nt) {
                e[mt][nt][0] = ex2f(S[mt][nt][0]);
                e[mt][nt][1] = ex2f(S[mt][nt][1]);
                e[mt][nt][2] = ex2f(S[mt][nt][2]);
                e[mt][nt][3] = ex2f(S[mt][nt][3]);
                int k = nt * 8 + t * 2;
                int slot = k ^ ((q & 3) << 3);   // (q+8)&3 == q&3 -> same slot
                *(float2*)(Es + n * 1024 + q * 32 + slot)       = make_float2(e[mt][nt][0], e[mt][nt][1]);
                *(float2*)(Es + n * 1024 + (q + 8) * 32 + slot) = make_float2(e[mt][nt][2], e[mt][nt][3]);
            }
        }
        __syncthreads();   // Es complete; K(kt) consumed

        // prefetch K(kt+1)
        {
            const int off = (kt + 1 < 32) ? (kt + 1) * 1024 : 0;
#pragma unroll
            for (int c = 0; c < 4; ++c) {
                cp16(smc + dstKV[c], sKh[c] + off);
                cp16(smc + 16384 + dstKV[c], sKl[c] + off);
            }
            cp_commit();
        }

        // Rs pass (slot-linear: swizzle is a per-row permutation)
#pragma unroll
        for (int pp = 0; pp < 4; ++pp) {
            int p = tid + pp * 256;
            float s = Es[p] + Es[1024 + p] + Es[2048 + p] + Es[3072 + p]
                    + Es[4096 + p] + Es[5120 + p] + Es[6144 + p] + Es[7168 + p];
            Rs[p] = __fdividef(1.0f, s);
        }
        cp_wait<1>();      // V(kt) done (older than K(kt+1))
        __syncthreads();   // Rs + V visible

        // ---- Phase B: W = e*r (bf16 split in-register), PV MMAs ----
        unsigned vhf[2][2][4], vlf[2][2][4];
#pragma unroll
        for (int grp = 0; grp < 2; ++grp)
#pragma unroll
            for (int j = 0; j < 2; ++j) {
                ldsm4(vhf[grp][j][0], vhf[grp][j][1], vhf[grp][j][2], vhf[grp][j][3], bVh + ldo[grp][j]);
                ldsm4(vlf[grp][j][0], vlf[grp][j][1], vlf[grp][j][2], vlf[grp][j][3], bVl + ldo[grp][j]);
            }
        unsigned Wh[2][2][4], Wl[2][2][4];
#pragma unroll
        for (int mt = 0; mt < 2; ++mt) {
            int q = mt * 16 + g;
#pragma unroll
            for (int nt = 0; nt < 4; ++nt) {
                int k = nt * 8 + t * 2;
                int slot = k ^ ((q & 3) << 3);
                float2 rA = *(const float2*)(Rs + q * 32 + slot);
                float2 rB = *(const float2*)(Rs + (q + 8) * 32 + slot);
                float w0 = e[mt][nt][0] * rA.x, w1 = e[mt][nt][1] * rA.y;
                float w2 = e[mt][nt][2] * rB.x, w3 = e[mt][nt][3] * rB.y;
                unsigned p01 = packbf(w0, w1);
                unsigned p23 = packbf(w2, w3);
                unsigned r01 = packbf(w0 - bflo(p01), w1 - bfhi(p01));
                unsigned r23 = packbf(w2 - bflo(p23), w3 - bfhi(p23));
                int j = nt >> 1, sub = nt & 1;
                Wh[mt][j][sub * 2 + 0] = p01; Wh[mt][j][sub * 2 + 1] = p23;
                Wl[mt][j][sub * 2 + 0] = r01; Wl[mt][j][sub * 2 + 1] = r23;
            }
        }
#pragma unroll
        for (int mt = 0; mt < 2; ++mt)
#pragma unroll
            for (int dg = 0; dg < 2; ++dg)
#pragma unroll
                for (int sub = 0; sub < 2; ++sub) {
                    float* d = out[mt][dg * 2 + sub];
#pragma unroll
                    for (int j = 0; j < 2; ++j) {
                        mma16816(d, Wh[mt][j], &vhf[dg][j][sub * 2]);
                        mma16816(d, Wh[mt][j], &vlf[dg][j][sub * 2]);
                        mma16816(d, Wl[mt][j], &vhf[dg][j][sub * 2]);
                    }
                }
    }
    cp_wait<0>();   // drain trailing K prefetch before exit

    // ---- epilogue: scrambled output c = n*32+qt, hw = q*32 + d ----
    float* obase = attnf + ((size_t)(b * 256 + n * 32 + qt)) * 1024;
#pragma unroll
    for (int mt = 0; mt < 2; ++mt) {
        int q = mt * 16 + g;
#pragma unroll
        for (int nt = 0; nt < 4; ++nt) {
            int d = nt * 8 + t * 2;
            *(float2*)(obase + q * 32 + d)       = make_float2(out[mt][nt][0], out[mt][nt][1]);
            *(float2*)(obase + (q + 8) * 32 + d) = make_float2(out[mt][nt][2], out[mt][nt][3]);
        }
    }
}

// ---------------------------------------------------------------------------
// Launch
// ---------------------------------------------------------------------------
extern "C" void kernel_launch(void* const* d_in, const int* in_sizes, int n_in,
                              void* d_out, int out_size)
{
    (void)in_sizes; (void)n_in; (void)out_size;
    const float* x      = (const float*)d_in[0];
    const float* w_qkv  = (const float*)d_in[1];
    const float* b_qkv  = (const float*)d_in[2];
    const float* w_attn = (const float*)d_in[3];
    const float* b_attn = (const float*)d_in[4];
    float* out = (float*)d_out;

    float *qkv, *attnf;
    __nv_bfloat16 *xh, *xl, *ah, *al, *wqh, *wql, *wah, *wal;
    __nv_bfloat16 *qTh, *qTl, *kTh, *kTl, *vvh, *vvl;
    cudaGetSymbolAddress((void**)&qkv, g_qkv);
    cudaGetSymbolAddress((void**)&attnf, g_attnf);
    cudaGetSymbolAddress((void**)&xh, g_xT_hi);
    cudaGetSymbolAddress((void**)&xl, g_xT_lo);
    cudaGetSymbolAddress((void**)&ah, g_aT_hi);
    cudaGetSymbolAddress((void**)&al, g_aT_lo);
    cudaGetSymbolAddress((void**)&wqh, g_wq_hi);
    cudaGetSymbolAddress((void**)&wql, g_wq_lo);
    cudaGetSymbolAddress((void**)&wah, g_wa_hi);
    cudaGetSymbolAddress((void**)&wal, g_wa_lo);
    cudaGetSymbolAddress((void**)&qTh, g_qT_hi);
    cudaGetSymbolAddress((void**)&qTl, g_qT_lo);
    cudaGetSymbolAddress((void**)&kTh, g_kT_hi);
    cudaGetSymbolAddress((void**)&kTl, g_kT_lo);
    cudaGetSymbolAddress((void**)&vvh, g_v_hi);
    cudaGetSymbolAddress((void**)&vvl, g_v_lo);

    cudaFuncSetAttribute(attn_mma_kernel,
                         cudaFuncAttributeMaxDynamicSharedMemorySize, 102400);

    // 0) split weights; transpose+split x
    wsplit_kernel<<<(768 * 512 + 255) / 256, 256>>>(w_qkv, wqh, wql, 768 * 512);
    wsplit_kernel<<<(512 * 256 + 255) / 256, 256>>>(w_attn, wah, wal, 512 * 256);
    tsplit_kernel<<<dim3(32, 16, 8), dim3(32, 8)>>>(x, xh, xl, 512, 1024);

    // 1) QKV projection (tensor core) + bias, Q pre-scaled 1/sqrt(32)/ln2
    mma_gemm<512, true><<<dim3(8, 6, 8), 256>>>(wqh, wql, xh, xl, b_qkv, qkv, 768);

    // 1b) build attention operands (bf16 hi/lo; Q/K transposed per head)
    prep_kernel<<<dim3(32, 24, 8), dim3(32, 8)>>>(qkv, qTh, qTl, kTh, kTl, vvh, vvl);

    // 2) tensor-core fused attention (head-softmax via exp2 + Es/Rs exchange)
    attn_mma_kernel<<<dim3(32, 8), 256, 102400>>>(qTh, qTl, kTh, kTl, vvh, vvl, attnf);

    // 2b) transpose + split attention output
    tsplit_kernel<<<dim3(32, 8, 8), dim3(32, 8)>>>(attnf, ah, al, 256, 1024);

    // 3) output projection (tensor core) + bias
    mma_gemm<256, false><<<dim3(8, 4, 8), 256>>>(wah, wal, ah, al, b_attn, out, 512);
}